// round 10
// baseline (speedup 1.0000x reference)
#include <cuda_runtime.h>
#include <cuda_bf16.h>
#include <stdint.h>

#define Bq 4
#define Sq 2048
#define Eq 1024
#define Hq 16

#define SW128(o) ((o) ^ (((o) >> 3) & 0x70))
#define SW256(o) ((o) ^ (((o) >> 4) & 0x70))

// ---------------- scratch ----------------
__device__ float g_Q[Bq*Hq*Sq*64];
__device__ float g_K[Bq*Hq*Sq*64];
__device__ float g_V[Bq*Hq*Sq*64];
__device__ float g_ctx[(size_t)Bq*Sq*Eq];
__device__ float g_proj[(size_t)Bq*Sq*Eq];
__device__ float g_rowmax[Bq*Hq*Sq];
__device__ float g_rinv[Bq*Hq*Sq];
__device__ float2 g_pstat[(size_t)Bq*Hq*Sq*64];   // 64 partial (max,sumexp) per row

// ---------------- mma / ldmatrix helpers ----------------
__device__ __forceinline__ void ldsm4(uint32_t& r0, uint32_t& r1, uint32_t& r2, uint32_t& r3, uint32_t a) {
    asm volatile("ldmatrix.sync.aligned.m8n8.x4.shared.b16 {%0,%1,%2,%3},[%4];"
                 : "=r"(r0), "=r"(r1), "=r"(r2), "=r"(r3) : "r"(a));
}
__device__ __forceinline__ void ldsm2(uint32_t& r0, uint32_t& r1, uint32_t a) {
    asm volatile("ldmatrix.sync.aligned.m8n8.x2.shared.b16 {%0,%1},[%2];"
                 : "=r"(r0), "=r"(r1) : "r"(a));
}
__device__ __forceinline__ void ldsm2t(uint32_t& r0, uint32_t& r1, uint32_t a) {
    asm volatile("ldmatrix.sync.aligned.m8n8.x2.trans.shared.b16 {%0,%1},[%2];"
                 : "=r"(r0), "=r"(r1) : "r"(a));
}
__device__ __forceinline__ void mmab(float* c, const uint32_t* a, const uint32_t* b) {
    asm volatile("mma.sync.aligned.m16n8k16.row.col.f32.bf16.bf16.f32 "
                 "{%0,%1,%2,%3},{%4,%5,%6,%7},{%8,%9},{%0,%1,%2,%3};"
                 : "+f"(c[0]), "+f"(c[1]), "+f"(c[2]), "+f"(c[3])
                 : "r"(a[0]), "r"(a[1]), "r"(a[2]), "r"(a[3]), "r"(b[0]), "r"(b[1]));
}
__device__ __forceinline__ uint32_t smaddr(const void* p) {
    return (uint32_t)__cvta_generic_to_shared(p);
}
__device__ __forceinline__ void split4(float4 v, uint2& h, uint2& l) {
    __nv_bfloat16 h0 = __float2bfloat16(v.x), h1 = __float2bfloat16(v.y);
    __nv_bfloat16 h2 = __float2bfloat16(v.z), h3 = __float2bfloat16(v.w);
    __nv_bfloat16 l0 = __float2bfloat16(v.x - __bfloat162float(h0));
    __nv_bfloat16 l1 = __float2bfloat16(v.y - __bfloat162float(h1));
    __nv_bfloat16 l2 = __float2bfloat16(v.z - __bfloat162float(h2));
    __nv_bfloat16 l3 = __float2bfloat16(v.w - __bfloat162float(h3));
    __nv_bfloat162 ph0(h0, h1), ph1(h2, h3), pl0(l0, l1), pl1(l2, l3);
    h.x = *(uint32_t*)&ph0; h.y = *(uint32_t*)&ph1;
    l.x = *(uint32_t*)&pl0; l.y = *(uint32_t*)&pl1;
}
// split fp32 pair -> packed bf16x2 hi + lo
__device__ __forceinline__ void pk2bf(float a, float b, uint32_t& h, uint32_t& l) {
    __nv_bfloat16 ha = __float2bfloat16(a), hb = __float2bfloat16(b);
    __nv_bfloat16 la = __float2bfloat16(a - __bfloat162float(ha));
    __nv_bfloat16 lb = __float2bfloat16(b - __bfloat162float(hb));
    __nv_bfloat162 ph(ha, hb), pl(la, lb);
    h = *(uint32_t*)&ph; l = *(uint32_t*)&pl;
}

// ---------------- block reductions (ln kernel) ----------------
__device__ __forceinline__ float block_sum(float v) {
    __shared__ float sh[33];
    int lane = threadIdx.x & 31, w = threadIdx.x >> 5;
    #pragma unroll
    for (int o = 16; o; o >>= 1) v += __shfl_xor_sync(0xffffffffu, v, o);
    __syncthreads();
    if (lane == 0) sh[w] = v;
    __syncthreads();
    if (w == 0) {
        float x = (lane < 8) ? sh[lane] : 0.0f;
        #pragma unroll
        for (int o = 4; o; o >>= 1) x += __shfl_xor_sync(0xffffffffu, x, o);
        if (lane == 0) sh[32] = x;
    }
    __syncthreads();
    return sh[32];
}

// ---------------- projections / output GEMM, double-buffered (R7 config), fused QKV ----------------
__global__ void __launch_bounds__(256) gemm8192(const float* __restrict__ A0,
                                                const float* __restrict__ A1,
                                                const float* __restrict__ A2,
                                                const float* __restrict__ W0,
                                                const float* __restrict__ W1,
                                                const float* __restrict__ W2,
                                                int modeBase) {
    extern __shared__ char smraw[];
    int mode = modeBase + blockIdx.z;
    const float* Ap = (mode == 0) ? A0 : (mode == 1) ? A1 : (mode == 2) ? A2 : g_ctx;
    const float* W  = (mode == 1) ? W1 : (mode == 2) ? W2 : W0;
    int t = threadIdx.x, lane = t & 31, wid = t >> 5;
    int wm = wid >> 2, wn = wid & 3;
    int m0 = blockIdx.y * 128, n0 = blockIdx.x * 128;
    int ar = t >> 4, ac4 = (t & 15) * 4;
    int bk = t >> 5, bc4 = (t & 31) * 4;
    uint32_t sBase = smaddr(smraw);

    float4 pa[8], pb[8];
    float acc[4][4][4];
    #pragma unroll
    for (int i = 0; i < 4; i++)
        #pragma unroll
        for (int j = 0; j < 4; j++)
            #pragma unroll
            for (int e = 0; e < 4; e++) acc[i][j][e] = 0.0f;

    #pragma unroll
    for (int p = 0; p < 8; p++) {
        pa[p] = *(const float4*)&Ap[(size_t)(m0 + ar + 16 * p) * 1024 + ac4];
        pb[p] = *(const float4*)&W[(size_t)(bk + 8 * p) * 1024 + n0 + bc4];
    }

    for (int kt = 0; kt < 16; kt++) {
        int buf = kt & 1;
        char* Ah = smraw + buf * 65536;
        char* Al = Ah + 16384;
        char* Bh = Al + 16384;
        char* Bl = Bh + 16384;
        #pragma unroll
        for (int p = 0; p < 8; p++) {
            uint2 h, l;
            split4(pa[p], h, l);
            uint32_t off = SW128((ar + 16 * p) * 128 + ac4 * 2);
            *(uint2*)(Ah + off) = h; *(uint2*)(Al + off) = l;
            split4(pb[p], h, l);
            uint32_t offb = SW256((bk + 8 * p) * 256 + bc4 * 2);
            *(uint2*)(Bh + offb) = h; *(uint2*)(Bl + offb) = l;
        }
        __syncthreads();
        if (kt < 15) {
            #pragma unroll
            for (int p = 0; p < 8; p++) {
                pa[p] = *(const float4*)&Ap[(size_t)(m0 + ar + 16 * p) * 1024 + (kt + 1) * 64 + ac4];
                pb[p] = *(const float4*)&W[(size_t)((kt + 1) * 64 + bk + 8 * p) * 1024 + n0 + bc4];
            }
        }
        uint32_t sAh = sBase + buf * 65536, sAl = sAh + 16384;
        uint32_t sBh = sAl + 16384, sBl = sBh + 16384;
        #pragma unroll
        for (int ks = 0; ks < 4; ks++) {
            uint32_t bhf[4][2], blf[4][2];
            #pragma unroll
            for (int in = 0; in < 4; in++) {
                int krow = ks * 16 + (lane & 15);
                int nb = (wn * 32 + in * 8) * 2;
                uint32_t off = SW256(krow * 256 + nb);
                ldsm2t(bhf[in][0], bhf[in][1], sBh + off);
                ldsm2t(blf[in][0], blf[in][1], sBl + off);
            }
            #pragma unroll
            for (int im = 0; im < 4; im++) {
                int arow = wm * 64 + im * 16 + (lane & 15);
                int acb = (ks * 16 + ((lane >> 4) << 3)) * 2;
                uint32_t off = SW128(arow * 128 + acb);
                uint32_t ah[4], al[4];
                ldsm4(ah[0], ah[1], ah[2], ah[3], sAh + off);
                ldsm4(al[0], al[1], al[2], al[3], sAl + off);
                #pragma unroll
                for (int in = 0; in < 4; in++) {
                    mmab(acc[im][in], ah, bhf[in]);
                    mmab(acc[im][in], al, bhf[in]);
                    mmab(acc[im][in], ah, blf[in]);
                }
            }
        }
    }

    int g = lane >> 2, c2 = (lane & 3) * 2;
    #pragma unroll
    for (int im = 0; im < 4; im++)
        #pragma unroll
        for (int in = 0; in < 4; in++)
            #pragma unroll
            for (int hh = 0; hh < 2; hh++) {
                int m = m0 + wm * 64 + im * 16 + g + hh * 8;
                int n = n0 + wn * 32 + in * 8 + c2;
                float2 v = make_float2(acc[im][in][hh * 2], acc[im][in][hh * 2 + 1]);
                if (mode <= 2) {
                    float* O = (mode == 0) ? g_Q : (mode == 1) ? g_K : g_V;
                    int b = m >> 11, s = m & 2047;
                    int h = n >> 6, d = n & 63;
                    *(float2*)&O[((size_t)(b * Hq + h) * Sq + s) * 64 + d] = v;
                } else {
                    *(float2*)&g_proj[(size_t)m * 1024 + n] = v;
                }
            }
}

// ---------------- scores: Q K^T (scaled+masked) -> attn, with partial row stats ----------------
__global__ void __launch_bounds__(256, 2) scores_kernel(const unsigned char* __restrict__ mask,
                                                        float* __restrict__ attn) {
    extern __shared__ char smraw[];
    char* Qh = smraw;                 // [128][64] SW128 bf16
    char* Ql = Qh + 16384;
    char* Kh = Ql + 16384;            // [128 kcol][64 d]
    char* Kl = Kh + 16384;
    int t = threadIdx.x, lane = t & 31, wid = t >> 5;
    int wm = wid >> 2, wn = wid & 3;
    int bh = blockIdx.z, q0 = blockIdx.y * 128, k0 = blockIdx.x * 128;
    size_t base = (size_t)bh * Sq * 64;
    uint32_t sQh = smaddr(Qh), sQl = smaddr(Ql), sKh = smaddr(Kh), sKl = smaddr(Kl);

    #pragma unroll
    for (int p = 0; p < 8; p++) {
        int r = (t >> 4) + 16 * p, c4 = (t & 15) * 4;
        uint32_t off = SW128(r * 128 + c4 * 2);
        float4 qv = *(const float4*)&g_Q[base + (size_t)(q0 + r) * 64 + c4];
        uint2 h, l; split4(qv, h, l);
        *(uint2*)(Qh + off) = h; *(uint2*)(Ql + off) = l;
        float4 kv = *(const float4*)&g_K[base + (size_t)(k0 + r) * 64 + c4];
        split4(kv, h, l);
        *(uint2*)(Kh + off) = h; *(uint2*)(Kl + off) = l;
    }
    __syncthreads();

    float acc[4][4][4];
    #pragma unroll
    for (int i = 0; i < 4; i++)
        #pragma unroll
        for (int j = 0; j < 4; j++)
            #pragma unroll
            for (int e = 0; e < 4; e++) acc[i][j][e] = 0.0f;

    #pragma unroll
    for (int ks = 0; ks < 4; ks++) {
        uint32_t bhf[4][2], blf[4][2];
        #pragma unroll
        for (int in = 0; in < 4; in++) {
            int nrow = wn * 32 + in * 8 + (lane & 7);
            int cb = (ks * 16 + (lane & 8)) * 2;
            uint32_t off = SW128(nrow * 128 + cb);
            ldsm2(bhf[in][0], bhf[in][1], sKh + off);
            ldsm2(blf[in][0], blf[in][1], sKl + off);
        }
        #pragma unroll
        for (int im = 0; im < 4; im++) {
            int arow = wm * 64 + im * 16 + (lane & 15);
            int acb = (ks * 16 + ((lane >> 4) << 3)) * 2;
            uint32_t off = SW128(arow * 128 + acb);
            uint32_t ah[4], al[4];
            ldsm4(ah[0], ah[1], ah[2], ah[3], sQh + off);
            ldsm4(al[0], al[1], al[2], al[3], sQl + off);
            #pragma unroll
            for (int in = 0; in < 4; in++) {
                mmab(acc[im][in], ah, bhf[in]);
                mmab(acc[im][in], al, bhf[in]);
                mmab(acc[im][in], ah, blf[in]);
            }
        }
    }

    int b = bh >> 4;
    int g = lane >> 2, c2 = (lane & 3) * 2;
    #pragma unroll
    for (int im = 0; im < 4; im++)
        #pragma unroll
        for (int hh = 0; hh < 2; hh++) {
            int q = q0 + wm * 64 + im * 16 + g + hh * 8;
            float vals[8];
            #pragma unroll
            for (int in = 0; in < 4; in++) {
                int kc = k0 + wn * 32 + in * 8 + c2;
                unsigned short mk = *(const unsigned short*)&mask[(size_t)b * Sq * Sq + (size_t)q * Sq + kc];
                float2 v;
                v.x = (mk & 0xffu) ? -1e9f : acc[im][in][hh * 2] * 0.125f;
                v.y = ((mk >> 8) & 0xffu) ? -1e9f : acc[im][in][hh * 2 + 1] * 0.125f;
                *(float2*)&attn[(size_t)bh * Sq * Sq + (size_t)q * Sq + kc] = v;
                vals[in * 2] = v.x; vals[in * 2 + 1] = v.y;
            }
            float m = vals[0];
            #pragma unroll
            for (int i = 1; i < 8; i++) m = fmaxf(m, vals[i]);
            m = fmaxf(m, __shfl_xor_sync(0xffffffffu, m, 1));
            m = fmaxf(m, __shfl_xor_sync(0xffffffffu, m, 2));
            float s = 0.0f;
            #pragma unroll
            for (int i = 0; i < 8; i++) s += __expf(vals[i] - m);
            s += __shfl_xor_sync(0xffffffffu, s, 1);
            s += __shfl_xor_sync(0xffffffffu, s, 2);
            if ((lane & 3) == 0)
                g_pstat[((size_t)bh * Sq + q) * 64 + blockIdx.x * 4 + wn] = make_float2(m, s);
        }
}

// ---------------- fold 64 partials per row -> rowmax, rinv ----------------
__global__ void __launch_bounds__(256) reduce_stats() {
    int r = blockIdx.x * 8 + (threadIdx.x >> 5);
    int lane = threadIdx.x & 31;
    float2 a = g_pstat[(size_t)r * 64 + lane];
    float2 b = g_pstat[(size_t)r * 64 + 32 + lane];
    float m = fmaxf(a.x, b.x);
    #pragma unroll
    for (int o = 16; o; o >>= 1) m = fmaxf(m, __shfl_xor_sync(0xffffffffu, m, o));
    float s = a.y * __expf(a.x - m) + b.y * __expf(b.x - m);
    #pragma unroll
    for (int o = 16; o; o >>= 1) s += __shfl_xor_sync(0xffffffffu, s, o);
    if (lane == 0) { g_rowmax[r] = m; g_rinv[r] = 1.0f / s; }
}

// ---------------- normalize attn + context = P @ V ----------------
// P fragments built directly in registers (no P smem); only V staged in smem (2x16KB).
// warp w owns q rows [w*16, w*16+16), all 64 n columns.
__global__ void __launch_bounds__(256, 2) av_kernel(float* __restrict__ attn) {
    extern __shared__ char smraw[];   // [2][Vh 8KB | Vl 8KB] = 32768 B
    int t = threadIdx.x, lane = t & 31, wid = t >> 5;
    int g = lane >> 2, c2 = (lane & 3) * 2;
    int bh = blockIdx.y, q0 = blockIdx.x * 128;
    size_t abase = (size_t)bh * Sq * Sq;
    size_t vbase = (size_t)bh * Sq * 64;
    int qr0 = q0 + wid * 16 + g;      // fragment row 0
    int qr1 = qr0 + 8;                // fragment row 1
    size_t srow0 = abase + (size_t)qr0 * Sq;
    size_t srow1 = abase + (size_t)qr1 * Sq;
    int rbase = bh * Sq;
    float m0 = g_rowmax[rbase + qr0 - q0 + q0];   // = g_rowmax[bh*Sq + qr0]
    float i0 = g_rinv[rbase + qr0 - q0 + q0];
    float m1 = g_rowmax[rbase + qr1 - q0 + q0];
    float i1 = g_rinv[rbase + qr1 - q0 + q0];

    float acc[8][4];
    #pragma unroll
    for (int i = 0; i < 8; i++)
        #pragma unroll
        for (int e = 0; e < 4; e++) acc[i][e] = 0.0f;

    int vr = t >> 4, vc4 = (t & 15) * 4;
    float4 vv[4];
    #pragma unroll
    for (int p = 0; p < 4; p++)
        vv[p] = *(const float4*)&g_V[vbase + (size_t)(vr + 16 * p) * 64 + vc4];

    for (int kt = 0; kt < 32; kt++) {
        char* Vh = smraw + (kt & 1) * 16384;
        char* Vl = Vh + 8192;
        #pragma unroll
        for (int p = 0; p < 4; p++) {
            uint2 h, l; split4(vv[p], h, l);
            uint32_t off = SW128((vr + 16 * p) * 128 + vc4 * 2);
            *(uint2*)(Vh + off) = h; *(uint2*)(Vl + off) = l;
        }
        __syncthreads();
        if (kt < 31) {
            #pragma unroll
            for (int p = 0; p < 4; p++)
                vv[p] = *(const float4*)&g_V[vbase + (size_t)((kt + 1) * 64 + vr + 16 * p) * 64 + vc4];
        }
        uint32_t sVh = smaddr(Vh), sVl = smaddr(Vl);
        #pragma unroll
        for (int ks = 0; ks < 4; ks++) {
            // A fragments direct from global raw scores
            int kc = kt * 64 + ks * 16 + c2;
            float2 s00 = *(const float2*)&attn[srow0 + kc];
            float2 s01 = *(const float2*)&attn[srow0 + kc + 8];
            float2 s10 = *(const float2*)&attn[srow1 + kc];
            float2 s11 = *(const float2*)&attn[srow1 + kc + 8];
            float2 p00, p01, p10, p11;
            p00.x = __expf(s00.x - m0) * i0; p00.y = __expf(s00.y - m0) * i0;
            p01.x = __expf(s01.x - m0) * i0; p01.y = __expf(s01.y - m0) * i0;
            p10.x = __expf(s10.x - m1) * i1; p10.y = __expf(s10.y - m1) * i1;
            p11.x = __expf(s11.x - m1) * i1; p11.y = __expf(s11.y - m1) * i1;
            *(float2*)&attn[srow0 + kc] = p00;
            *(float2*)&attn[srow0 + kc + 8] = p01;
            *(float2*)&attn[srow1 + kc] = p10;
            *(float2*)&attn[srow1 + kc + 8] = p11;
            uint32_t ah[4], al[4];
            pk2bf(p00.x, p00.y, ah[0], al[0]);
            pk2bf(p10.x, p10.y, ah[1], al[1]);
            pk2bf(p01.x, p01.y, ah[2], al[2]);
            pk2bf(p11.x, p11.y, ah[3], al[3]);
            // B fragments + MMA, 8 n-tiles
            #pragma unroll
            for (int in = 0; in < 8; in++) {
                int krow = ks * 16 + (lane & 15);
                uint32_t off = SW128(krow * 128 + in * 16);
                uint32_t bh0, bh1, bl0, bl1;
                ldsm2t(bh0, bh1, sVh + off);
                ldsm2t(bl0, bl1, sVl + off);
                uint32_t bhf[2] = {bh0, bh1}, blf[2] = {bl0, bl1};
                mmab(acc[in], ah, bhf);
                mmab(acc[in], al, bhf);
                mmab(acc[in], ah, blf);
            }
        }
    }

    int b = bh >> 4, h = bh & 15;
    #pragma unroll
    for (int in = 0; in < 8; in++)
        #pragma unroll
        for (int hh = 0; hh < 2; hh++) {
            int q = q0 + wid * 16 + g + hh * 8;
            int n = in * 8 + c2;
            float2 v = make_float2(acc[in][hh * 2], acc[in][hh * 2 + 1]);
            *(float2*)&g_ctx[(size_t)(b * Sq + q) * 1024 + h * 64 + n] = v;
        }
}

// ---------------- residual + LayerNorm ----------------
__global__ void __launch_bounds__(256) ln_kernel(const float* __restrict__ inQ,
                                                 const float* __restrict__ gamma,
                                                 const float* __restrict__ beta,
                                                 float* __restrict__ out) {
    int m = blockIdx.x, t = threadIdx.x;
    size_t base = (size_t)m * 1024;
    float x[4];
    float s = 0.0f;
    #pragma unroll
    for (int i = 0; i < 4; i++) {
        int c = i * 256 + t;
        x[i] = g_proj[base + c] + inQ[base + c];
        s += x[i];
    }
    s = block_sum(s);
    float mu = s * (1.0f / 1024.0f);
    float s2 = 0.0f;
    #pragma unroll
    for (int i = 0; i < 4; i++) { float d = x[i] - mu; s2 += d * d; }
    s2 = block_sum(s2);
    float rstd = rsqrtf(s2 * (1.0f / 1024.0f) + 1e-5f);
    #pragma unroll
    for (int i = 0; i < 4; i++) {
        int c = i * 256 + t;
        out[base + c] = (x[i] - mu) * rstd * gamma[c] + beta[c];
    }
}

// ---------------- launch ----------------
extern "C" void kernel_launch(void* const* d_in, const int* in_sizes, int n_in,
                              void* d_out, int out_size) {
    const float* inQ = (const float*)d_in[0];
    const float* inK = (const float*)d_in[1];
    const float* inV = (const float*)d_in[2];
    const unsigned char* mask = (const unsigned char*)d_in[3];
    const float* wQ = (const float*)d_in[4];
    const float* wK = (const float*)d_in[5];
    const float* wV = (const float*)d_in[6];
    const float* wO = (const float*)d_in[7];
    const float* gamma = (const float*)d_in[8];
    const float* beta = (const float*)d_in[9];
    float* out = (float*)d_out;
    float* attn = out + (size_t)Bq * Sq * Eq;

    const int GEMM_SMEM = 131072;  // double buffer (R7 best)
    const int SC_SMEM   = 65536;
    const int AV_SMEM   = 32768;   // V only, double-buffered
    cudaFuncSetAttribute(gemm8192, cudaFuncAttributeMaxDynamicSharedMemorySize, GEMM_SMEM);
    cudaFuncSetAttribute(scores_kernel, cudaFuncAttributeMaxDynamicSharedMemorySize, SC_SMEM);
    cudaFuncSetAttribute(av_kernel, cudaFuncAttributeMaxDynamicSharedMemorySize, AV_SMEM);

    dim3 blk(256);
    gemm8192<<<dim3(8, 64, 3), blk, GEMM_SMEM>>>(inQ, inK, inV, wQ, wK, wV, 0);
    scores_kernel<<<dim3(16, 16, 64), blk, SC_SMEM>>>(mask, attn);
    reduce_stats<<<Bq * Hq * Sq / 8, blk>>>();
    av_kernel<<<dim3(16, 64), blk, AV_SMEM>>>(attn);
    gemm8192<<<dim3(8, 64, 1), blk, GEMM_SMEM>>>(nullptr, nullptr, nullptr, wO, nullptr, nullptr, 3);
    ln_kernel<<<Bq * Sq, blk>>>(inQ, gamma, beta, out);
}

// round 11
// speedup vs baseline: 1.7842x; 1.7842x over previous
#include <cuda_runtime.h>
#include <cuda_bf16.h>
#include <stdint.h>

#define Bq 4
#define Sq 2048
#define Eq 1024
#define Hq 16

#define SW64(o)  ((o) ^ (((o) >> 3) & 0x30))
#define SW128(o) ((o) ^ (((o) >> 3) & 0x70))
#define SW256(o) ((o) ^ (((o) >> 4) & 0x70))

// ---------------- scratch ----------------
__device__ float g_Q[Bq*Hq*Sq*64];
__device__ float g_K[Bq*Hq*Sq*64];
__device__ float g_V[Bq*Hq*Sq*64];
__device__ float g_ctx[(size_t)Bq*Sq*Eq];
__device__ float g_proj[(size_t)Bq*Sq*Eq];
__device__ float g_rowmax[Bq*Hq*Sq];
__device__ float g_rinv[Bq*Hq*Sq];
__device__ float2 g_pstat[(size_t)Bq*Hq*Sq*64];   // 64 partial (max,sumexp) per row

// ---------------- mma / ldmatrix helpers ----------------
__device__ __forceinline__ void ldsm4(uint32_t& r0, uint32_t& r1, uint32_t& r2, uint32_t& r3, uint32_t a) {
    asm volatile("ldmatrix.sync.aligned.m8n8.x4.shared.b16 {%0,%1,%2,%3},[%4];"
                 : "=r"(r0), "=r"(r1), "=r"(r2), "=r"(r3) : "r"(a));
}
__device__ __forceinline__ void ldsm2(uint32_t& r0, uint32_t& r1, uint32_t a) {
    asm volatile("ldmatrix.sync.aligned.m8n8.x2.shared.b16 {%0,%1},[%2];"
                 : "=r"(r0), "=r"(r1) : "r"(a));
}
__device__ __forceinline__ void ldsm2t(uint32_t& r0, uint32_t& r1, uint32_t a) {
    asm volatile("ldmatrix.sync.aligned.m8n8.x2.trans.shared.b16 {%0,%1},[%2];"
                 : "=r"(r0), "=r"(r1) : "r"(a));
}
__device__ __forceinline__ void mmab(float* c, const uint32_t* a, const uint32_t* b) {
    asm volatile("mma.sync.aligned.m16n8k16.row.col.f32.bf16.bf16.f32 "
                 "{%0,%1,%2,%3},{%4,%5,%6,%7},{%8,%9},{%0,%1,%2,%3};"
                 : "+f"(c[0]), "+f"(c[1]), "+f"(c[2]), "+f"(c[3])
                 : "r"(a[0]), "r"(a[1]), "r"(a[2]), "r"(a[3]), "r"(b[0]), "r"(b[1]));
}
__device__ __forceinline__ uint32_t smaddr(const void* p) {
    return (uint32_t)__cvta_generic_to_shared(p);
}
__device__ __forceinline__ void split4(float4 v, uint2& h, uint2& l) {
    __nv_bfloat16 h0 = __float2bfloat16(v.x), h1 = __float2bfloat16(v.y);
    __nv_bfloat16 h2 = __float2bfloat16(v.z), h3 = __float2bfloat16(v.w);
    __nv_bfloat16 l0 = __float2bfloat16(v.x - __bfloat162float(h0));
    __nv_bfloat16 l1 = __float2bfloat16(v.y - __bfloat162float(h1));
    __nv_bfloat16 l2 = __float2bfloat16(v.z - __bfloat162float(h2));
    __nv_bfloat16 l3 = __float2bfloat16(v.w - __bfloat162float(h3));
    __nv_bfloat162 ph0(h0, h1), ph1(h2, h3), pl0(l0, l1), pl1(l2, l3);
    h.x = *(uint32_t*)&ph0; h.y = *(uint32_t*)&ph1;
    l.x = *(uint32_t*)&pl0; l.y = *(uint32_t*)&pl1;
}

// ---------------- block reductions (ln kernel) ----------------
__device__ __forceinline__ float block_sum(float v) {
    __shared__ float sh[33];
    int lane = threadIdx.x & 31, w = threadIdx.x >> 5;
    #pragma unroll
    for (int o = 16; o; o >>= 1) v += __shfl_xor_sync(0xffffffffu, v, o);
    __syncthreads();
    if (lane == 0) sh[w] = v;
    __syncthreads();
    if (w == 0) {
        float x = (lane < 8) ? sh[lane] : 0.0f;
        #pragma unroll
        for (int o = 4; o; o >>= 1) x += __shfl_xor_sync(0xffffffffu, x, o);
        if (lane == 0) sh[32] = x;
    }
    __syncthreads();
    return sh[32];
}

// ---------------- projections / output GEMM ----------------
// k-step 32, double-buffered (2 x 32KB = 64KB), 2 CTAs/SM, fused QKV via grid.z
__global__ void __launch_bounds__(256, 2) gemm8192(const float* __restrict__ A0,
                                                   const float* __restrict__ A1,
                                                   const float* __restrict__ A2,
                                                   const float* __restrict__ W0,
                                                   const float* __restrict__ W1,
                                                   const float* __restrict__ W2,
                                                   int modeBase) {
    extern __shared__ char smraw[];
    int mode = modeBase + blockIdx.z;
    const float* Ap = (mode == 0) ? A0 : (mode == 1) ? A1 : (mode == 2) ? A2 : g_ctx;
    const float* W  = (mode == 1) ? W1 : (mode == 2) ? W2 : W0;
    int t = threadIdx.x, lane = t & 31, wid = t >> 5;
    int wm = wid >> 2, wn = wid & 3;                 // 2x4 warps, 64m x 32n each
    int m0 = blockIdx.y * 128, n0 = blockIdx.x * 128;
    int ar = t >> 1, acf = (t & 1) * 16;             // A: 128 rows, 2 thr/row, 16 floats each
    int bkr = t >> 3, bcf = (t & 7) * 16;            // B: 32 rows, 8 thr/row, 16 floats each
    uint32_t sBase = smaddr(smraw);
    // stage layout: Ah 8KB | Al 8KB | Bh 8KB | Bl 8KB  (32KB per stage)

    float4 pa[4], pb[4];
    float acc[4][4][4];
    #pragma unroll
    for (int i = 0; i < 4; i++)
        #pragma unroll
        for (int j = 0; j < 4; j++)
            #pragma unroll
            for (int e = 0; e < 4; e++) acc[i][j][e] = 0.0f;

    #pragma unroll
    for (int p = 0; p < 4; p++) {
        pa[p] = *(const float4*)&Ap[(size_t)(m0 + ar) * 1024 + acf + p * 4];
        pb[p] = *(const float4*)&W[(size_t)bkr * 1024 + n0 + bcf + p * 4];
    }

    for (int kt = 0; kt < 32; kt++) {
        int buf = kt & 1;
        char* Ah = smraw + buf * 32768;
        char* Al = Ah + 8192;
        char* Bh = Al + 8192;
        char* Bl = Bh + 8192;
        #pragma unroll
        for (int p = 0; p < 4; p++) {
            uint2 h, l;
            split4(pa[p], h, l);
            uint32_t off = SW64(ar * 64 + acf * 2 + p * 8);
            *(uint2*)(Ah + off) = h; *(uint2*)(Al + off) = l;
            split4(pb[p], h, l);
            uint32_t offb = SW256(bkr * 256 + bcf * 2 + p * 8);
            *(uint2*)(Bh + offb) = h; *(uint2*)(Bl + offb) = l;
        }
        __syncthreads();
        if (kt < 31) {
            #pragma unroll
            for (int p = 0; p < 4; p++) {
                pa[p] = *(const float4*)&Ap[(size_t)(m0 + ar) * 1024 + (kt + 1) * 32 + acf + p * 4];
                pb[p] = *(const float4*)&W[(size_t)((kt + 1) * 32 + bkr) * 1024 + n0 + bcf + p * 4];
            }
        }
        uint32_t sAh = sBase + buf * 32768, sAl = sAh + 8192;
        uint32_t sBh = sAl + 8192, sBl = sBh + 8192;
        #pragma unroll
        for (int ks = 0; ks < 2; ks++) {
            uint32_t bhf[4][2], blf[4][2];
            #pragma unroll
            for (int in = 0; in < 4; in++) {
                int krow = ks * 16 + (lane & 15);
                int nb = (wn * 32 + in * 8) * 2;
                uint32_t off = SW256(krow * 256 + nb);
                ldsm2t(bhf[in][0], bhf[in][1], sBh + off);
                ldsm2t(blf[in][0], blf[in][1], sBl + off);
            }
            #pragma unroll
            for (int im = 0; im < 4; im++) {
                int arow = wm * 64 + im * 16 + (lane & 15);
                int acb = (ks * 16 + ((lane >> 4) << 3)) * 2;
                uint32_t off = SW64(arow * 64 + acb);
                uint32_t ah[4], al[4];
                ldsm4(ah[0], ah[1], ah[2], ah[3], sAh + off);
                ldsm4(al[0], al[1], al[2], al[3], sAl + off);
                #pragma unroll
                for (int in = 0; in < 4; in++) {
                    mmab(acc[im][in], ah, bhf[in]);
                    mmab(acc[im][in], al, bhf[in]);
                    mmab(acc[im][in], ah, blf[in]);
                }
            }
        }
    }

    int g = lane >> 2, c2 = (lane & 3) * 2;
    #pragma unroll
    for (int im = 0; im < 4; im++)
        #pragma unroll
        for (int in = 0; in < 4; in++)
            #pragma unroll
            for (int hh = 0; hh < 2; hh++) {
                int m = m0 + wm * 64 + im * 16 + g + hh * 8;
                int n = n0 + wn * 32 + in * 8 + c2;
                float2 v = make_float2(acc[im][in][hh * 2], acc[im][in][hh * 2 + 1]);
                if (mode <= 2) {
                    float* O = (mode == 0) ? g_Q : (mode == 1) ? g_K : g_V;
                    int b = m >> 11, s = m & 2047;
                    int h = n >> 6, d = n & 63;
                    *(float2*)&O[((size_t)(b * Hq + h) * Sq + s) * 64 + d] = v;
                } else {
                    *(float2*)&g_proj[(size_t)m * 1024 + n] = v;
                }
            }
}

// ---------------- scores: Q K^T (scaled+masked) -> attn, with partial row stats (R7) ----------------
__global__ void __launch_bounds__(256, 2) scores_kernel(const unsigned char* __restrict__ mask,
                                                        float* __restrict__ attn) {
    extern __shared__ char smraw[];
    char* Qh = smraw;                 // [128][64] SW128 bf16
    char* Ql = Qh + 16384;
    char* Kh = Ql + 16384;            // [128 kcol][64 d]
    char* Kl = Kh + 16384;
    int t = threadIdx.x, lane = t & 31, wid = t >> 5;
    int wm = wid >> 2, wn = wid & 3;
    int bh = blockIdx.z, q0 = blockIdx.y * 128, k0 = blockIdx.x * 128;
    size_t base = (size_t)bh * Sq * 64;
    uint32_t sQh = smaddr(Qh), sQl = smaddr(Ql), sKh = smaddr(Kh), sKl = smaddr(Kl);

    #pragma unroll
    for (int p = 0; p < 8; p++) {
        int r = (t >> 4) + 16 * p, c4 = (t & 15) * 4;
        uint32_t off = SW128(r * 128 + c4 * 2);
        float4 qv = *(const float4*)&g_Q[base + (size_t)(q0 + r) * 64 + c4];
        uint2 h, l; split4(qv, h, l);
        *(uint2*)(Qh + off) = h; *(uint2*)(Ql + off) = l;
        float4 kv = *(const float4*)&g_K[base + (size_t)(k0 + r) * 64 + c4];
        split4(kv, h, l);
        *(uint2*)(Kh + off) = h; *(uint2*)(Kl + off) = l;
    }
    __syncthreads();

    float acc[4][4][4];
    #pragma unroll
    for (int i = 0; i < 4; i++)
        #pragma unroll
        for (int j = 0; j < 4; j++)
            #pragma unroll
            for (int e = 0; e < 4; e++) acc[i][j][e] = 0.0f;

    #pragma unroll
    for (int ks = 0; ks < 4; ks++) {
        uint32_t bhf[4][2], blf[4][2];
        #pragma unroll
        for (int in = 0; in < 4; in++) {
            int nrow = wn * 32 + in * 8 + (lane & 7);
            int cb = (ks * 16 + (lane & 8)) * 2;
            uint32_t off = SW128(nrow * 128 + cb);
            ldsm2(bhf[in][0], bhf[in][1], sKh + off);
            ldsm2(blf[in][0], blf[in][1], sKl + off);
        }
        #pragma unroll
        for (int im = 0; im < 4; im++) {
            int arow = wm * 64 + im * 16 + (lane & 15);
            int acb = (ks * 16 + ((lane >> 4) << 3)) * 2;
            uint32_t off = SW128(arow * 128 + acb);
            uint32_t ah[4], al[4];
            ldsm4(ah[0], ah[1], ah[2], ah[3], sQh + off);
            ldsm4(al[0], al[1], al[2], al[3], sQl + off);
            #pragma unroll
            for (int in = 0; in < 4; in++) {
                mmab(acc[im][in], ah, bhf[in]);
                mmab(acc[im][in], al, bhf[in]);
                mmab(acc[im][in], ah, blf[in]);
            }
        }
    }

    int b = bh >> 4;
    int g = lane >> 2, c2 = (lane & 3) * 2;
    #pragma unroll
    for (int im = 0; im < 4; im++)
        #pragma unroll
        for (int hh = 0; hh < 2; hh++) {
            int q = q0 + wm * 64 + im * 16 + g + hh * 8;
            float vals[8];
            #pragma unroll
            for (int in = 0; in < 4; in++) {
                int kc = k0 + wn * 32 + in * 8 + c2;
                unsigned short mk = *(const unsigned short*)&mask[(size_t)b * Sq * Sq + (size_t)q * Sq + kc];
                float2 v;
                v.x = (mk & 0xffu) ? -1e9f : acc[im][in][hh * 2] * 0.125f;
                v.y = ((mk >> 8) & 0xffu) ? -1e9f : acc[im][in][hh * 2 + 1] * 0.125f;
                *(float2*)&attn[(size_t)bh * Sq * Sq + (size_t)q * Sq + kc] = v;
                vals[in * 2] = v.x; vals[in * 2 + 1] = v.y;
            }
            float m = vals[0];
            #pragma unroll
            for (int i = 1; i < 8; i++) m = fmaxf(m, vals[i]);
            m = fmaxf(m, __shfl_xor_sync(0xffffffffu, m, 1));
            m = fmaxf(m, __shfl_xor_sync(0xffffffffu, m, 2));
            float s = 0.0f;
            #pragma unroll
            for (int i = 0; i < 8; i++) s += __expf(vals[i] - m);
            s += __shfl_xor_sync(0xffffffffu, s, 1);
            s += __shfl_xor_sync(0xffffffffu, s, 2);
            if ((lane & 3) == 0)
                g_pstat[((size_t)bh * Sq + q) * 64 + blockIdx.x * 4 + wn] = make_float2(m, s);
        }
}

// ---------------- fold 64 partials per row -> rowmax, rinv ----------------
__global__ void __launch_bounds__(256) reduce_stats() {
    int r = blockIdx.x * 8 + (threadIdx.x >> 5);
    int lane = threadIdx.x & 31;
    float2 a = g_pstat[(size_t)r * 64 + lane];
    float2 b = g_pstat[(size_t)r * 64 + 32 + lane];
    float m = fmaxf(a.x, b.x);
    #pragma unroll
    for (int o = 16; o; o >>= 1) m = fmaxf(m, __shfl_xor_sync(0xffffffffu, m, o));
    float s = a.y * __expf(a.x - m) + b.y * __expf(b.x - m);
    #pragma unroll
    for (int o = 16; o; o >>= 1) s += __shfl_xor_sync(0xffffffffu, s, o);
    if (lane == 0) { g_rowmax[r] = m; g_rinv[r] = 1.0f / s; }
}

// ---------------- normalize attn + context = P @ V ----------------
// k-step 32, double-buffered (2 x 24KB = 48KB), 2 CTAs/SM.
__global__ void __launch_bounds__(256, 2) av_kernel(float* __restrict__ attn) {
    extern __shared__ char smraw[];
    // stage: Ph 8KB | Pl 8KB | Vh 4KB | Vl 4KB  (24KB per stage)
    int t = threadIdx.x, lane = t & 31, wid = t >> 5;
    int wm = wid >> 1, wn = wid & 1;            // 4x2 warps, 32q x 32n each
    int bh = blockIdx.y, q0 = blockIdx.x * 128;
    size_t abase = (size_t)bh * Sq * Sq;
    size_t vbase = (size_t)bh * Sq * 64;
    int r0 = bh * Sq + q0;
    int lr = t >> 1, pcf = (t & 1) * 16;        // P: 128 rows, 2 thr/row, 16 floats each
    int vr = t >> 3, vcf = (t & 7) * 8;         // V: 32 rows, 8 thr/row, 8 floats each
    uint32_t sBase = smaddr(smraw);

    float mx = g_rowmax[r0 + lr];
    float ri = g_rinv[r0 + lr];

    float acc[2][4][4];
    #pragma unroll
    for (int i = 0; i < 2; i++)
        #pragma unroll
        for (int j = 0; j < 4; j++)
            #pragma unroll
            for (int e = 0; e < 4; e++) acc[i][j][e] = 0.0f;

    float4 sv[4], vv[2];
    #pragma unroll
    for (int p = 0; p < 4; p++)
        sv[p] = *(const float4*)&attn[abase + (size_t)(q0 + lr) * Sq + pcf + p * 4];
    #pragma unroll
    for (int p = 0; p < 2; p++)
        vv[p] = *(const float4*)&g_V[vbase + (size_t)vr * 64 + vcf + p * 4];

    for (int kt = 0; kt < 64; kt++) {
        int buf = kt & 1;
        char* Ph = smraw + buf * 24576;
        char* Pl = Ph + 8192;
        char* Vh = Pl + 8192;
        char* Vl = Vh + 4096;
        // exp-normalize current P tile, write probs back, split into smem
        #pragma unroll
        for (int p = 0; p < 4; p++) {
            float4 pv;
            pv.x = __expf(sv[p].x - mx) * ri;
            pv.y = __expf(sv[p].y - mx) * ri;
            pv.z = __expf(sv[p].z - mx) * ri;
            pv.w = __expf(sv[p].w - mx) * ri;
            *(float4*)&attn[abase + (size_t)(q0 + lr) * Sq + kt * 32 + pcf + p * 4] = pv;
            uint2 h, l; split4(pv, h, l);
            uint32_t off = SW64(lr * 64 + pcf * 2 + p * 8);
            *(uint2*)(Ph + off) = h; *(uint2*)(Pl + off) = l;
        }
        #pragma unroll
        for (int p = 0; p < 2; p++) {
            uint2 h, l; split4(vv[p], h, l);
            uint32_t off = SW128(vr * 128 + vcf * 2 + p * 8);
            *(uint2*)(Vh + off) = h; *(uint2*)(Vl + off) = l;
        }
        __syncthreads();
        if (kt < 63) {
            #pragma unroll
            for (int p = 0; p < 4; p++)
                sv[p] = *(const float4*)&attn[abase + (size_t)(q0 + lr) * Sq + (kt + 1) * 32 + pcf + p * 4];
            #pragma unroll
            for (int p = 0; p < 2; p++)
                vv[p] = *(const float4*)&g_V[vbase + (size_t)((kt + 1) * 32 + vr) * 64 + vcf + p * 4];
        }
        uint32_t sPh = sBase + buf * 24576, sPl = sPh + 8192;
        uint32_t sVh = sPl + 8192, sVl = sVh + 4096;
        #pragma unroll
        for (int ks = 0; ks < 2; ks++) {
            uint32_t bhf[4][2], blf[4][2];
            #pragma unroll
            for (int in = 0; in < 4; in++) {
                int krow = ks * 16 + (lane & 15);
                int nb = (wn * 32 + in * 8) * 2;
                uint32_t off = SW128(krow * 128 + nb);
                ldsm2t(bhf[in][0], bhf[in][1], sVh + off);
                ldsm2t(blf[in][0], blf[in][1], sVl + off);
            }
            #pragma unroll
            for (int im = 0; im < 2; im++) {
                int arow = wm * 32 + im * 16 + (lane & 15);
                int acb = (ks * 16 + ((lane >> 4) << 3)) * 2;
                uint32_t off = SW64(arow * 64 + acb);
                uint32_t ah[4], al[4];
                ldsm4(ah[0], ah[1], ah[2], ah[3], sPh + off);
                ldsm4(al[0], al[1], al[2], al[3], sPl + off);
                #pragma unroll
                for (int in = 0; in < 4; in++) {
                    mmab(acc[im][in], ah, bhf[in]);
                    mmab(acc[im][in], al, bhf[in]);
                    mmab(acc[im][in], ah, blf[in]);
                }
            }
        }
    }

    int b = bh >> 4, h = bh & 15;
    int g = lane >> 2, c2 = (lane & 3) * 2;
    #pragma unroll
    for (int im = 0; im < 2; im++)
        #pragma unroll
        for (int in = 0; in < 4; in++)
            #pragma unroll
            for (int hh = 0; hh < 2; hh++) {
                int q = q0 + wm * 32 + im * 16 + g + hh * 8;
                int n = wn * 32 + in * 8 + c2;
                float2 v = make_float2(acc[im][in][hh * 2], acc[im][in][hh * 2 + 1]);
                *(float2*)&g_ctx[(size_t)(b * Sq + q) * 1024 + h * 64 + n] = v;
            }
}

// ---------------- residual + LayerNorm ----------------
__global__ void __launch_bounds__(256) ln_kernel(const float* __restrict__ inQ,
                                                 const float* __restrict__ gamma,
                                                 const float* __restrict__ beta,
                                                 float* __restrict__ out) {
    int m = blockIdx.x, t = threadIdx.x;
    size_t base = (size_t)m * 1024;
    float x[4];
    float s = 0.0f;
    #pragma unroll
    for (int i = 0; i < 4; i++) {
        int c = i * 256 + t;
        x[i] = g_proj[base + c] + inQ[base + c];
        s += x[i];
    }
    s = block_sum(s);
    float mu = s * (1.0f / 1024.0f);
    float s2 = 0.0f;
    #pragma unroll
    for (int i = 0; i < 4; i++) { float d = x[i] - mu; s2 += d * d; }
    s2 = block_sum(s2);
    float rstd = rsqrtf(s2 * (1.0f / 1024.0f) + 1e-5f);
    #pragma unroll
    for (int i = 0; i < 4; i++) {
        int c = i * 256 + t;
        out[base + c] = (x[i] - mu) * rstd * gamma[c] + beta[c];
    }
}

// ---------------- launch ----------------
extern "C" void kernel_launch(void* const* d_in, const int* in_sizes, int n_in,
                              void* d_out, int out_size) {
    const float* inQ = (const float*)d_in[0];
    const float* inK = (const float*)d_in[1];
    const float* inV = (const float*)d_in[2];
    const unsigned char* mask = (const unsigned char*)d_in[3];
    const float* wQ = (const float*)d_in[4];
    const float* wK = (const float*)d_in[5];
    const float* wV = (const float*)d_in[6];
    const float* wO = (const float*)d_in[7];
    const float* gamma = (const float*)d_in[8];
    const float* beta = (const float*)d_in[9];
    float* out = (float*)d_out;
    float* attn = out + (size_t)Bq * Sq * Eq;

    const int GEMM_SMEM = 65536;   // 2 x 32KB stages, 2 CTAs/SM
    const int SC_SMEM   = 65536;
    const int AV_SMEM   = 49152;   // 2 x 24KB stages, 2 CTAs/SM
    cudaFuncSetAttribute(gemm8192, cudaFuncAttributeMaxDynamicSharedMemorySize, GEMM_SMEM);
    cudaFuncSetAttribute(scores_kernel, cudaFuncAttributeMaxDynamicSharedMemorySize, SC_SMEM);
    cudaFuncSetAttribute(av_kernel, cudaFuncAttributeMaxDynamicSharedMemorySize, AV_SMEM);

    dim3 blk(256);
    gemm8192<<<dim3(8, 64, 3), blk, GEMM_SMEM>>>(inQ, inK, inV, wQ, wK, wV, 0);
    scores_kernel<<<dim3(16, 16, 64), blk, SC_SMEM>>>(mask, attn);
    reduce_stats<<<Bq * Hq * Sq / 8, blk>>>();
    av_kernel<<<dim3(16, 64), blk, AV_SMEM>>>(attn);
    gemm8192<<<dim3(8, 64, 1), blk, GEMM_SMEM>>>(nullptr, nullptr, nullptr, wO, nullptr, nullptr, 3);
    ln_kernel<<<Bq * Sq, blk>>>(inQ, gamma, beta, out);
}

// round 12
// speedup vs baseline: 1.9032x; 1.0667x over previous
#include <cuda_runtime.h>
#include <cuda_bf16.h>
#include <stdint.h>

#define Bq 4
#define Sq 2048
#define Eq 1024
#define Hq 16

#define SW128(o) ((o) ^ (((o) >> 3) & 0x70))
#define SW256(o) ((o) ^ (((o) >> 4) & 0x70))

// ---------------- scratch ----------------
__device__ float g_Q[Bq*Hq*Sq*64];
__device__ float g_K[Bq*Hq*Sq*64];
__device__ float g_V[Bq*Hq*Sq*64];
__device__ float g_ctx[(size_t)Bq*Sq*Eq];
__device__ float g_proj[(size_t)Bq*Sq*Eq];
__device__ float g_rowmax[Bq*Hq*Sq];
__device__ float g_rinv[Bq*Hq*Sq];
__device__ float2 g_pstat[(size_t)Bq*Hq*Sq*64];   // 64 partial (max,sumexp) per row

// ---------------- mma / ldmatrix helpers ----------------
__device__ __forceinline__ void ldsm4(uint32_t& r0, uint32_t& r1, uint32_t& r2, uint32_t& r3, uint32_t a) {
    asm volatile("ldmatrix.sync.aligned.m8n8.x4.shared.b16 {%0,%1,%2,%3},[%4];"
                 : "=r"(r0), "=r"(r1), "=r"(r2), "=r"(r3) : "r"(a));
}
__device__ __forceinline__ void ldsm2(uint32_t& r0, uint32_t& r1, uint32_t a) {
    asm volatile("ldmatrix.sync.aligned.m8n8.x2.shared.b16 {%0,%1},[%2];"
                 : "=r"(r0), "=r"(r1) : "r"(a));
}
__device__ __forceinline__ void ldsm2t(uint32_t& r0, uint32_t& r1, uint32_t a) {
    asm volatile("ldmatrix.sync.aligned.m8n8.x2.trans.shared.b16 {%0,%1},[%2];"
                 : "=r"(r0), "=r"(r1) : "r"(a));
}
__device__ __forceinline__ void mmab(float* c, const uint32_t* a, const uint32_t* b) {
    asm volatile("mma.sync.aligned.m16n8k16.row.col.f32.bf16.bf16.f32 "
                 "{%0,%1,%2,%3},{%4,%5,%6,%7},{%8,%9},{%0,%1,%2,%3};"
                 : "+f"(c[0]), "+f"(c[1]), "+f"(c[2]), "+f"(c[3])
                 : "r"(a[0]), "r"(a[1]), "r"(a[2]), "r"(a[3]), "r"(b[0]), "r"(b[1]));
}
__device__ __forceinline__ uint32_t smaddr(const void* p) {
    return (uint32_t)__cvta_generic_to_shared(p);
}
__device__ __forceinline__ void split4(float4 v, uint2& h, uint2& l) {
    __nv_bfloat16 h0 = __float2bfloat16(v.x), h1 = __float2bfloat16(v.y);
    __nv_bfloat16 h2 = __float2bfloat16(v.z), h3 = __float2bfloat16(v.w);
    __nv_bfloat16 l0 = __float2bfloat16(v.x - __bfloat162float(h0));
    __nv_bfloat16 l1 = __float2bfloat16(v.y - __bfloat162float(h1));
    __nv_bfloat16 l2 = __float2bfloat16(v.z - __bfloat162float(h2));
    __nv_bfloat16 l3 = __float2bfloat16(v.w - __bfloat162float(h3));
    __nv_bfloat162 ph0(h0, h1), ph1(h2, h3), pl0(l0, l1), pl1(l2, l3);
    h.x = *(uint32_t*)&ph0; h.y = *(uint32_t*)&ph1;
    l.x = *(uint32_t*)&pl0; l.y = *(uint32_t*)&pl1;
}

// ---------------- block reductions (ln kernel) ----------------
__device__ __forceinline__ float block_sum(float v) {
    __shared__ float sh[33];
    int lane = threadIdx.x & 31, w = threadIdx.x >> 5;
    #pragma unroll
    for (int o = 16; o; o >>= 1) v += __shfl_xor_sync(0xffffffffu, v, o);
    __syncthreads();
    if (lane == 0) sh[w] = v;
    __syncthreads();
    if (w == 0) {
        float x = (lane < 8) ? sh[lane] : 0.0f;
        #pragma unroll
        for (int o = 4; o; o >>= 1) x += __shfl_xor_sync(0xffffffffu, x, o);
        if (lane == 0) sh[32] = x;
    }
    __syncthreads();
    return sh[32];
}

// ---------------- projections / output GEMM ----------------
// R7 pipeline (double-buffered 2x64KB, 1 sync/iter), 512 threads / 16 warps.
__global__ void __launch_bounds__(512) gemm8192(const float* __restrict__ A0,
                                                const float* __restrict__ A1,
                                                const float* __restrict__ A2,
                                                const float* __restrict__ W0,
                                                const float* __restrict__ W1,
                                                const float* __restrict__ W2,
                                                int modeBase) {
    extern __shared__ char smraw[];
    int mode = modeBase + blockIdx.z;
    const float* Ap = (mode == 0) ? A0 : (mode == 1) ? A1 : (mode == 2) ? A2 : g_ctx;
    const float* W  = (mode == 1) ? W1 : (mode == 2) ? W2 : W0;
    int t = threadIdx.x, lane = t & 31, wid = t >> 5;
    int wm = wid >> 2, wn = wid & 3;                 // 4x4 warps, 32m x 32n each
    int m0 = blockIdx.y * 128, n0 = blockIdx.x * 128;
    int ar = t >> 2, acf = (t & 3) * 16;             // A: 128 rows, 4 thr/row, 16 floats each
    int bk = t >> 3, bcf = (t & 7) * 16;             // B: 64 rows, 8 thr/row, 16 floats each
    uint32_t sBase = smaddr(smraw);

    float4 pa[4], pb[4];
    float acc[2][4][4];
    #pragma unroll
    for (int i = 0; i < 2; i++)
        #pragma unroll
        for (int j = 0; j < 4; j++)
            #pragma unroll
            for (int e = 0; e < 4; e++) acc[i][j][e] = 0.0f;

    #pragma unroll
    for (int p = 0; p < 4; p++) {
        pa[p] = *(const float4*)&Ap[(size_t)(m0 + ar) * 1024 + acf + p * 4];
        pb[p] = *(const float4*)&W[(size_t)bk * 1024 + n0 + bcf + p * 4];
    }

    for (int kt = 0; kt < 16; kt++) {
        int buf = kt & 1;
        char* Ah = smraw + buf * 65536;
        char* Al = Ah + 16384;
        char* Bh = Al + 16384;
        char* Bl = Bh + 16384;
        #pragma unroll
        for (int p = 0; p < 4; p++) {
            uint2 h, l;
            split4(pa[p], h, l);
            uint32_t off = SW128(ar * 128 + (acf + p * 4) * 2);
            *(uint2*)(Ah + off) = h; *(uint2*)(Al + off) = l;
            split4(pb[p], h, l);
            uint32_t offb = SW256(bk * 256 + (bcf + p * 4) * 2);
            *(uint2*)(Bh + offb) = h; *(uint2*)(Bl + offb) = l;
        }
        __syncthreads();
        if (kt < 15) {
            #pragma unroll
            for (int p = 0; p < 4; p++) {
                pa[p] = *(const float4*)&Ap[(size_t)(m0 + ar) * 1024 + (kt + 1) * 64 + acf + p * 4];
                pb[p] = *(const float4*)&W[(size_t)((kt + 1) * 64 + bk) * 1024 + n0 + bcf + p * 4];
            }
        }
        uint32_t sAh = sBase + buf * 65536, sAl = sAh + 16384;
        uint32_t sBh = sAl + 16384, sBl = sBh + 16384;
        #pragma unroll
        for (int ks = 0; ks < 4; ks++) {
            uint32_t bhf[4][2], blf[4][2];
            #pragma unroll
            for (int in = 0; in < 4; in++) {
                int krow = ks * 16 + (lane & 15);
                int nb = (wn * 32 + in * 8) * 2;
                uint32_t off = SW256(krow * 256 + nb);
                ldsm2t(bhf[in][0], bhf[in][1], sBh + off);
                ldsm2t(blf[in][0], blf[in][1], sBl + off);
            }
            #pragma unroll
            for (int im = 0; im < 2; im++) {
                int arow = wm * 32 + im * 16 + (lane & 15);
                int acb = (ks * 16 + ((lane >> 4) << 3)) * 2;
                uint32_t off = SW128(arow * 128 + acb);
                uint32_t ah[4], al[4];
                ldsm4(ah[0], ah[1], ah[2], ah[3], sAh + off);
                ldsm4(al[0], al[1], al[2], al[3], sAl + off);
                #pragma unroll
                for (int in = 0; in < 4; in++) {
                    mmab(acc[im][in], ah, bhf[in]);
                    mmab(acc[im][in], al, bhf[in]);
                    mmab(acc[im][in], ah, blf[in]);
                }
            }
        }
    }

    int g = lane >> 2, c2 = (lane & 3) * 2;
    #pragma unroll
    for (int im = 0; im < 2; im++)
        #pragma unroll
        for (int in = 0; in < 4; in++)
            #pragma unroll
            for (int hh = 0; hh < 2; hh++) {
                int m = m0 + wm * 32 + im * 16 + g + hh * 8;
                int n = n0 + wn * 32 + in * 8 + c2;
                float2 v = make_float2(acc[im][in][hh * 2], acc[im][in][hh * 2 + 1]);
                if (mode <= 2) {
                    float* O = (mode == 0) ? g_Q : (mode == 1) ? g_K : g_V;
                    int b = m >> 11, s = m & 2047;
                    int h = n >> 6, d = n & 63;
                    *(float2*)&O[((size_t)(b * Hq + h) * Sq + s) * 64 + d] = v;
                } else {
                    *(float2*)&g_proj[(size_t)m * 1024 + n] = v;
                }
            }
}

// ---------------- scores: Q K^T (scaled+masked) -> attn, with partial row stats (R7, unchanged) ----------------
__global__ void __launch_bounds__(256, 2) scores_kernel(const unsigned char* __restrict__ mask,
                                                        float* __restrict__ attn) {
    extern __shared__ char smraw[];
    char* Qh = smraw;                 // [128][64] SW128 bf16
    char* Ql = Qh + 16384;
    char* Kh = Ql + 16384;            // [128 kcol][64 d]
    char* Kl = Kh + 16384;
    int t = threadIdx.x, lane = t & 31, wid = t >> 5;
    int wm = wid >> 2, wn = wid & 3;
    int bh = blockIdx.z, q0 = blockIdx.y * 128, k0 = blockIdx.x * 128;
    size_t base = (size_t)bh * Sq * 64;
    uint32_t sQh = smaddr(Qh), sQl = smaddr(Ql), sKh = smaddr(Kh), sKl = smaddr(Kl);

    #pragma unroll
    for (int p = 0; p < 8; p++) {
        int r = (t >> 4) + 16 * p, c4 = (t & 15) * 4;
        uint32_t off = SW128(r * 128 + c4 * 2);
        float4 qv = *(const float4*)&g_Q[base + (size_t)(q0 + r) * 64 + c4];
        uint2 h, l; split4(qv, h, l);
        *(uint2*)(Qh + off) = h; *(uint2*)(Ql + off) = l;
        float4 kv = *(const float4*)&g_K[base + (size_t)(k0 + r) * 64 + c4];
        split4(kv, h, l);
        *(uint2*)(Kh + off) = h; *(uint2*)(Kl + off) = l;
    }
    __syncthreads();

    float acc[4][4][4];
    #pragma unroll
    for (int i = 0; i < 4; i++)
        #pragma unroll
        for (int j = 0; j < 4; j++)
            #pragma unroll
            for (int e = 0; e < 4; e++) acc[i][j][e] = 0.0f;

    #pragma unroll
    for (int ks = 0; ks < 4; ks++) {
        uint32_t bhf[4][2], blf[4][2];
        #pragma unroll
        for (int in = 0; in < 4; in++) {
            int nrow = wn * 32 + in * 8 + (lane & 7);
            int cb = (ks * 16 + (lane & 8)) * 2;
            uint32_t off = SW128(nrow * 128 + cb);
            ldsm2(bhf[in][0], bhf[in][1], sKh + off);
            ldsm2(blf[in][0], blf[in][1], sKl + off);
        }
        #pragma unroll
        for (int im = 0; im < 4; im++) {
            int arow = wm * 64 + im * 16 + (lane & 15);
            int acb = (ks * 16 + ((lane >> 4) << 3)) * 2;
            uint32_t off = SW128(arow * 128 + acb);
            uint32_t ah[4], al[4];
            ldsm4(ah[0], ah[1], ah[2], ah[3], sQh + off);
            ldsm4(al[0], al[1], al[2], al[3], sQl + off);
            #pragma unroll
            for (int in = 0; in < 4; in++) {
                mmab(acc[im][in], ah, bhf[in]);
                mmab(acc[im][in], al, bhf[in]);
                mmab(acc[im][in], ah, blf[in]);
            }
        }
    }

    int b = bh >> 4;
    int g = lane >> 2, c2 = (lane & 3) * 2;
    #pragma unroll
    for (int im = 0; im < 4; im++)
        #pragma unroll
        for (int hh = 0; hh < 2; hh++) {
            int q = q0 + wm * 64 + im * 16 + g + hh * 8;
            float vals[8];
            #pragma unroll
            for (int in = 0; in < 4; in++) {
                int kc = k0 + wn * 32 + in * 8 + c2;
                unsigned short mk = *(const unsigned short*)&mask[(size_t)b * Sq * Sq + (size_t)q * Sq + kc];
                float2 v;
                v.x = (mk & 0xffu) ? -1e9f : acc[im][in][hh * 2] * 0.125f;
                v.y = ((mk >> 8) & 0xffu) ? -1e9f : acc[im][in][hh * 2 + 1] * 0.125f;
                *(float2*)&attn[(size_t)bh * Sq * Sq + (size_t)q * Sq + kc] = v;
                vals[in * 2] = v.x; vals[in * 2 + 1] = v.y;
            }
            float m = vals[0];
            #pragma unroll
            for (int i = 1; i < 8; i++) m = fmaxf(m, vals[i]);
            m = fmaxf(m, __shfl_xor_sync(0xffffffffu, m, 1));
            m = fmaxf(m, __shfl_xor_sync(0xffffffffu, m, 2));
            float s = 0.0f;
            #pragma unroll
            for (int i = 0; i < 8; i++) s += __expf(vals[i] - m);
            s += __shfl_xor_sync(0xffffffffu, s, 1);
            s += __shfl_xor_sync(0xffffffffu, s, 2);
            if ((lane & 3) == 0)
                g_pstat[((size_t)bh * Sq + q) * 64 + blockIdx.x * 4 + wn] = make_float2(m, s);
        }
}

// ---------------- fold 64 partials per row -> rowmax, rinv ----------------
__global__ void __launch_bounds__(256) reduce_stats() {
    int r = blockIdx.x * 8 + (threadIdx.x >> 5);
    int lane = threadIdx.x & 31;
    float2 a = g_pstat[(size_t)r * 64 + lane];
    float2 b = g_pstat[(size_t)r * 64 + 32 + lane];
    float m = fmaxf(a.x, b.x);
    #pragma unroll
    for (int o = 16; o; o >>= 1) m = fmaxf(m, __shfl_xor_sync(0xffffffffu, m, o));
    float s = a.y * __expf(a.x - m) + b.y * __expf(b.x - m);
    #pragma unroll
    for (int o = 16; o; o >>= 1) s += __shfl_xor_sync(0xffffffffu, s, o);
    if (lane == 0) { g_rowmax[r] = m; g_rinv[r] = 1.0f / s; }
}

// ---------------- normalize attn + context = P @ V ----------------
// R7 pipeline (double-buffered 2x48KB, 1 sync/iter), 512 threads / 16 warps.
__global__ void __launch_bounds__(512) av_kernel(float* __restrict__ attn) {
    extern __shared__ char smraw[];
    int t = threadIdx.x, lane = t & 31, wid = t >> 5;
    int wm = wid >> 1, wn = wid & 1;            // 8x2 warps, 16q x 32n each
    int bh = blockIdx.y, q0 = blockIdx.x * 128;
    size_t abase = (size_t)bh * Sq * Sq;
    size_t vbase = (size_t)bh * Sq * 64;
    int r0 = bh * Sq + q0;
    uint32_t sBase = smaddr(smraw);
    int lr = t >> 2, pcf = (t & 3) * 16;        // P: 128 rows, 4 thr/row, 16 floats each
    int vr = t >> 3, vcf = (t & 7) * 8;         // V: 64 rows, 8 thr/row, 8 floats each

    float mx = g_rowmax[r0 + lr];
    float ri = g_rinv[r0 + lr];

    float acc[4][4];
    #pragma unroll
    for (int j = 0; j < 4; j++)
        #pragma unroll
        for (int e = 0; e < 4; e++) acc[j][e] = 0.0f;

    float4 sv[4], vv[2];
    #pragma unroll
    for (int p = 0; p < 4; p++)
        sv[p] = *(const float4*)&attn[abase + (size_t)(q0 + lr) * Sq + pcf + p * 4];
    #pragma unroll
    for (int p = 0; p < 2; p++)
        vv[p] = *(const float4*)&g_V[vbase + (size_t)vr * 64 + vcf + p * 4];

    for (int kt = 0; kt < 32; kt++) {
        int buf = kt & 1;
        char* Ph = smraw + buf * 49152;
        char* Pl = Ph + 16384;
        char* Vh = Pl + 16384;
        char* Vl = Vh + 8192;
        #pragma unroll
        for (int p = 0; p < 4; p++) {
            float4 pv;
            pv.x = __expf(sv[p].x - mx) * ri;
            pv.y = __expf(sv[p].y - mx) * ri;
            pv.z = __expf(sv[p].z - mx) * ri;
            pv.w = __expf(sv[p].w - mx) * ri;
            *(float4*)&attn[abase + (size_t)(q0 + lr) * Sq + kt * 64 + pcf + p * 4] = pv;
            uint2 h, l; split4(pv, h, l);
            uint32_t off = SW128(lr * 128 + (pcf + p * 4) * 2);
            *(uint2*)(Ph + off) = h; *(uint2*)(Pl + off) = l;
        }
        #pragma unroll
        for (int p = 0; p < 2; p++) {
            uint2 h, l; split4(vv[p], h, l);
            uint32_t off = SW128(vr * 128 + (vcf + p * 4) * 2);
            *(uint2*)(Vh + off) = h; *(uint2*)(Vl + off) = l;
        }
        __syncthreads();
        if (kt < 31) {
            #pragma unroll
            for (int p = 0; p < 4; p++)
                sv[p] = *(const float4*)&attn[abase + (size_t)(q0 + lr) * Sq + (kt + 1) * 64 + pcf + p * 4];
            #pragma unroll
            for (int p = 0; p < 2; p++)
                vv[p] = *(const float4*)&g_V[vbase + (size_t)((kt + 1) * 64 + vr) * 64 + vcf + p * 4];
        }
        uint32_t sPh = sBase + buf * 49152, sPl = sPh + 16384;
        uint32_t sVh = sPl + 16384, sVl = sVh + 8192;
        #pragma unroll
        for (int ks = 0; ks < 4; ks++) {
            uint32_t bhf[4][2], blf[4][2];
            #pragma unroll
            for (int in = 0; in < 4; in++) {
                int krow = ks * 16 + (lane & 15);
                int nb = (wn * 32 + in * 8) * 2;
                uint32_t off = SW128(krow * 128 + nb);
                ldsm2t(bhf[in][0], bhf[in][1], sVh + off);
                ldsm2t(blf[in][0], blf[in][1], sVl + off);
            }
            int arow = wm * 16 + (lane & 15);
            int acb = (ks * 16 + ((lane >> 4) << 3)) * 2;
            uint32_t off = SW128(arow * 128 + acb);
            uint32_t ah[4], al[4];
            ldsm4(ah[0], ah[1], ah[2], ah[3], sPh + off);
            ldsm4(al[0], al[1], al[2], al[3], sPl + off);
            #pragma unroll
            for (int in = 0; in < 4; in++) {
                mmab(acc[in], ah, bhf[in]);
                mmab(acc[in], al, bhf[in]);
                mmab(acc[in], ah, blf[in]);
            }
        }
    }

    int b = bh >> 4, h = bh & 15;
    int g = lane >> 2, c2 = (lane & 3) * 2;
    #pragma unroll
    for (int in = 0; in < 4; in++)
        #pragma unroll
        for (int hh = 0; hh < 2; hh++) {
            int q = q0 + wm * 16 + g + hh * 8;
            int n = wn * 32 + in * 8 + c2;
            float2 v = make_float2(acc[in][hh * 2], acc[in][hh * 2 + 1]);
            *(float2*)&g_ctx[(size_t)(b * Sq + q) * 1024 + h * 64 + n] = v;
        }
}

// ---------------- residual + LayerNorm ----------------
__global__ void __launch_bounds__(256) ln_kernel(const float* __restrict__ inQ,
                                                 const float* __restrict__ gamma,
                                                 const float* __restrict__ beta,
                                                 float* __restrict__ out) {
    int m = blockIdx.x, t = threadIdx.x;
    size_t base = (size_t)m * 1024;
    float x[4];
    float s = 0.0f;
    #pragma unroll
    for (int i = 0; i < 4; i++) {
        int c = i * 256 + t;
        x[i] = g_proj[base + c] + inQ[base + c];
        s += x[i];
    }
    s = block_sum(s);
    float mu = s * (1.0f / 1024.0f);
    float s2 = 0.0f;
    #pragma unroll
    for (int i = 0; i < 4; i++) { float d = x[i] - mu; s2 += d * d; }
    s2 = block_sum(s2);
    float rstd = rsqrtf(s2 * (1.0f / 1024.0f) + 1e-5f);
    #pragma unroll
    for (int i = 0; i < 4; i++) {
        int c = i * 256 + t;
        out[base + c] = (x[i] - mu) * rstd * gamma[c] + beta[c];
    }
}

// ---------------- launch ----------------
extern "C" void kernel_launch(void* const* d_in, const int* in_sizes, int n_in,
                              void* d_out, int out_size) {
    const float* inQ = (const float*)d_in[0];
    const float* inK = (const float*)d_in[1];
    const float* inV = (const float*)d_in[2];
    const unsigned char* mask = (const unsigned char*)d_in[3];
    const float* wQ = (const float*)d_in[4];
    const float* wK = (const float*)d_in[5];
    const float* wV = (const float*)d_in[6];
    const float* wO = (const float*)d_in[7];
    const float* gamma = (const float*)d_in[8];
    const float* beta = (const float*)d_in[9];
    float* out = (float*)d_out;
    float* attn = out + (size_t)Bq * Sq * Eq;

    const int GEMM_SMEM = 131072;  // 2 x 64KB stages (R7)
    const int SC_SMEM   = 65536;
    const int AV_SMEM   = 98304;   // 2 x 48KB stages (R7)
    cudaFuncSetAttribute(gemm8192, cudaFuncAttributeMaxDynamicSharedMemorySize, GEMM_SMEM);
    cudaFuncSetAttribute(scores_kernel, cudaFuncAttributeMaxDynamicSharedMemorySize, SC_SMEM);
    cudaFuncSetAttribute(av_kernel, cudaFuncAttributeMaxDynamicSharedMemorySize, AV_SMEM);

    gemm8192<<<dim3(8, 64, 3), 512, GEMM_SMEM>>>(inQ, inK, inV, wQ, wK, wV, 0);
    scores_kernel<<<dim3(16, 16, 64), 256, SC_SMEM>>>(mask, attn);
    reduce_stats<<<Bq * Hq * Sq / 8, 256>>>();
    av_kernel<<<dim3(16, 64), 512, AV_SMEM>>>(attn);
    gemm8192<<<dim3(8, 64, 1), 512, GEMM_SMEM>>>(nullptr, nullptr, nullptr, wO, nullptr, nullptr, 3);
    ln_kernel<<<Bq * Sq, 256>>>(inQ, gamma, beta, out);
}

// round 13
// speedup vs baseline: 2.0138x; 1.0581x over previous
#include <cuda_runtime.h>
#include <cuda_bf16.h>
#include <stdint.h>

#define Bq 4
#define Sq 2048
#define Eq 1024
#define Hq 16

#define SW128(o) ((o) ^ (((o) >> 3) & 0x70))
#define SW256(o) ((o) ^ (((o) >> 4) & 0x70))

// ---------------- scratch ----------------
__device__ float g_Q[Bq*Hq*Sq*64];
__device__ float g_K[Bq*Hq*Sq*64];
__device__ float g_V[Bq*Hq*Sq*64];
__device__ float g_ctx[(size_t)Bq*Sq*Eq];
__device__ float g_proj[(size_t)Bq*Sq*Eq];
__device__ float g_rowmax[Bq*Hq*Sq];
__device__ float g_rinv[Bq*Hq*Sq];
__device__ float2 g_pstat[(size_t)Bq*Hq*Sq*64];   // 64 partial (max,sumexp) per row

// ---------------- mma / ldmatrix helpers ----------------
__device__ __forceinline__ void ldsm4(uint32_t& r0, uint32_t& r1, uint32_t& r2, uint32_t& r3, uint32_t a) {
    asm volatile("ldmatrix.sync.aligned.m8n8.x4.shared.b16 {%0,%1,%2,%3},[%4];"
                 : "=r"(r0), "=r"(r1), "=r"(r2), "=r"(r3) : "r"(a));
}
__device__ __forceinline__ void ldsm2(uint32_t& r0, uint32_t& r1, uint32_t a) {
    asm volatile("ldmatrix.sync.aligned.m8n8.x2.shared.b16 {%0,%1},[%2];"
                 : "=r"(r0), "=r"(r1) : "r"(a));
}
__device__ __forceinline__ void ldsm2t(uint32_t& r0, uint32_t& r1, uint32_t a) {
    asm volatile("ldmatrix.sync.aligned.m8n8.x2.trans.shared.b16 {%0,%1},[%2];"
                 : "=r"(r0), "=r"(r1) : "r"(a));
}
__device__ __forceinline__ void mmab(float* c, const uint32_t* a, const uint32_t* b) {
    asm volatile("mma.sync.aligned.m16n8k16.row.col.f32.bf16.bf16.f32 "
                 "{%0,%1,%2,%3},{%4,%5,%6,%7},{%8,%9},{%0,%1,%2,%3};"
                 : "+f"(c[0]), "+f"(c[1]), "+f"(c[2]), "+f"(c[3])
                 : "r"(a[0]), "r"(a[1]), "r"(a[2]), "r"(a[3]), "r"(b[0]), "r"(b[1]));
}
__device__ __forceinline__ uint32_t smaddr(const void* p) {
    return (uint32_t)__cvta_generic_to_shared(p);
}
__device__ __forceinline__ void split4(float4 v, uint2& h, uint2& l) {
    __nv_bfloat16 h0 = __float2bfloat16(v.x), h1 = __float2bfloat16(v.y);
    __nv_bfloat16 h2 = __float2bfloat16(v.z), h3 = __float2bfloat16(v.w);
    __nv_bfloat16 l0 = __float2bfloat16(v.x - __bfloat162float(h0));
    __nv_bfloat16 l1 = __float2bfloat16(v.y - __bfloat162float(h1));
    __nv_bfloat16 l2 = __float2bfloat16(v.z - __bfloat162float(h2));
    __nv_bfloat16 l3 = __float2bfloat16(v.w - __bfloat162float(h3));
    __nv_bfloat162 ph0(h0, h1), ph1(h2, h3), pl0(l0, l1), pl1(l2, l3);
    h.x = *(uint32_t*)&ph0; h.y = *(uint32_t*)&ph1;
    l.x = *(uint32_t*)&pl0; l.y = *(uint32_t*)&pl1;
}
__device__ __forceinline__ void pk2bf(float a, float b, uint32_t& h, uint32_t& l) {
    __nv_bfloat16 ha = __float2bfloat16(a), hb = __float2bfloat16(b);
    __nv_bfloat16 la = __float2bfloat16(a - __bfloat162float(ha));
    __nv_bfloat16 lb = __float2bfloat16(b - __bfloat162float(hb));
    __nv_bfloat162 ph(ha, hb), pl(la, lb);
    h = *(uint32_t*)&ph; l = *(uint32_t*)&pl;
}

// ---------------- block reductions (ln kernel) ----------------
__device__ __forceinline__ float block_sum(float v) {
    __shared__ float sh[33];
    int lane = threadIdx.x & 31, w = threadIdx.x >> 5;
    #pragma unroll
    for (int o = 16; o; o >>= 1) v += __shfl_xor_sync(0xffffffffu, v, o);
    __syncthreads();
    if (lane == 0) sh[w] = v;
    __syncthreads();
    if (w == 0) {
        float x = (lane < 8) ? sh[lane] : 0.0f;
        #pragma unroll
        for (int o = 4; o; o >>= 1) x += __shfl_xor_sync(0xffffffffu, x, o);
        if (lane == 0) sh[32] = x;
    }
    __syncthreads();
    return sh[32];
}

// ---------------- projections / output GEMM (R7: 256 thr, double-buffered 2x64KB) ----------------
__global__ void __launch_bounds__(256) gemm8192(const float* __restrict__ A0,
                                                const float* __restrict__ A1,
                                                const float* __restrict__ A2,
                                                const float* __restrict__ W0,
                                                const float* __restrict__ W1,
                                                const float* __restrict__ W2,
                                                int modeBase) {
    extern __shared__ char smraw[];
    int mode = modeBase + blockIdx.z;
    const float* Ap = (mode == 0) ? A0 : (mode == 1) ? A1 : (mode == 2) ? A2 : g_ctx;
    const float* W  = (mode == 1) ? W1 : (mode == 2) ? W2 : W0;
    int t = threadIdx.x, lane = t & 31, wid = t >> 5;
    int wm = wid >> 2, wn = wid & 3;
    int m0 = blockIdx.y * 128, n0 = blockIdx.x * 128;
    int ar = t >> 4, ac4 = (t & 15) * 4;
    int bk = t >> 5, bc4 = (t & 31) * 4;
    uint32_t sBase = smaddr(smraw);

    float4 pa[8], pb[8];
    float acc[4][4][4];
    #pragma unroll
    for (int i = 0; i < 4; i++)
        #pragma unroll
        for (int j = 0; j < 4; j++)
            #pragma unroll
            for (int e = 0; e < 4; e++) acc[i][j][e] = 0.0f;

    #pragma unroll
    for (int p = 0; p < 8; p++) {
        pa[p] = *(const float4*)&Ap[(size_t)(m0 + ar + 16 * p) * 1024 + ac4];
        pb[p] = *(const float4*)&W[(size_t)(bk + 8 * p) * 1024 + n0 + bc4];
    }

    for (int kt = 0; kt < 16; kt++) {
        int buf = kt & 1;
        char* Ah = smraw + buf * 65536;
        char* Al = Ah + 16384;
        char* Bh = Al + 16384;
        char* Bl = Bh + 16384;
        #pragma unroll
        for (int p = 0; p < 8; p++) {
            uint2 h, l;
            split4(pa[p], h, l);
            uint32_t off = SW128((ar + 16 * p) * 128 + ac4 * 2);
            *(uint2*)(Ah + off) = h; *(uint2*)(Al + off) = l;
            split4(pb[p], h, l);
            uint32_t offb = SW256((bk + 8 * p) * 256 + bc4 * 2);
            *(uint2*)(Bh + offb) = h; *(uint2*)(Bl + offb) = l;
        }
        __syncthreads();
        if (kt < 15) {
            #pragma unroll
            for (int p = 0; p < 8; p++) {
                pa[p] = *(const float4*)&Ap[(size_t)(m0 + ar + 16 * p) * 1024 + (kt + 1) * 64 + ac4];
                pb[p] = *(const float4*)&W[(size_t)((kt + 1) * 64 + bk + 8 * p) * 1024 + n0 + bc4];
            }
        }
        uint32_t sAh = sBase + buf * 65536, sAl = sAh + 16384;
        uint32_t sBh = sAl + 16384, sBl = sBh + 16384;
        #pragma unroll
        for (int ks = 0; ks < 4; ks++) {
            uint32_t bhf[4][2], blf[4][2];
            #pragma unroll
            for (int in = 0; in < 4; in++) {
                int krow = ks * 16 + (lane & 15);
                int nb = (wn * 32 + in * 8) * 2;
                uint32_t off = SW256(krow * 256 + nb);
                ldsm2t(bhf[in][0], bhf[in][1], sBh + off);
                ldsm2t(blf[in][0], blf[in][1], sBl + off);
            }
            #pragma unroll
            for (int im = 0; im < 4; im++) {
                int arow = wm * 64 + im * 16 + (lane & 15);
                int acb = (ks * 16 + ((lane >> 4) << 3)) * 2;
                uint32_t off = SW128(arow * 128 + acb);
                uint32_t ah[4], al[4];
                ldsm4(ah[0], ah[1], ah[2], ah[3], sAh + off);
                ldsm4(al[0], al[1], al[2], al[3], sAl + off);
                #pragma unroll
                for (int in = 0; in < 4; in++) {
                    mmab(acc[im][in], ah, bhf[in]);
                    mmab(acc[im][in], al, bhf[in]);
                    mmab(acc[im][in], ah, blf[in]);
                }
            }
        }
    }

    int g = lane >> 2, c2 = (lane & 3) * 2;
    #pragma unroll
    for (int im = 0; im < 4; im++)
        #pragma unroll
        for (int in = 0; in < 4; in++)
            #pragma unroll
            for (int hh = 0; hh < 2; hh++) {
                int m = m0 + wm * 64 + im * 16 + g + hh * 8;
                int n = n0 + wn * 32 + in * 8 + c2;
                float2 v = make_float2(acc[im][in][hh * 2], acc[im][in][hh * 2 + 1]);
                if (mode <= 2) {
                    float* O = (mode == 0) ? g_Q : (mode == 1) ? g_K : g_V;
                    int b = m >> 11, s = m & 2047;
                    int h = n >> 6, d = n & 63;
                    *(float2*)&O[((size_t)(b * Hq + h) * Sq + s) * 64 + d] = v;
                } else {
                    *(float2*)&g_proj[(size_t)m * 1024 + n] = v;
                }
            }
}

// ---------------- pass A: stats-only scores (no attn store) ----------------
__global__ void __launch_bounds__(256, 2) scores_stats(const unsigned char* __restrict__ mask) {
    extern __shared__ char smraw[];
    char* Qh = smraw;
    char* Ql = Qh + 16384;
    char* Kh = Ql + 16384;
    char* Kl = Kh + 16384;
    int t = threadIdx.x, lane = t & 31, wid = t >> 5;
    int wm = wid >> 2, wn = wid & 3;
    int bh = blockIdx.z, q0 = blockIdx.y * 128, k0 = blockIdx.x * 128;
    size_t base = (size_t)bh * Sq * 64;
    uint32_t sQh = smaddr(Qh), sQl = smaddr(Ql), sKh = smaddr(Kh), sKl = smaddr(Kl);

    #pragma unroll
    for (int p = 0; p < 8; p++) {
        int r = (t >> 4) + 16 * p, c4 = (t & 15) * 4;
        uint32_t off = SW128(r * 128 + c4 * 2);
        float4 qv = *(const float4*)&g_Q[base + (size_t)(q0 + r) * 64 + c4];
        uint2 h, l; split4(qv, h, l);
        *(uint2*)(Qh + off) = h; *(uint2*)(Ql + off) = l;
        float4 kv = *(const float4*)&g_K[base + (size_t)(k0 + r) * 64 + c4];
        split4(kv, h, l);
        *(uint2*)(Kh + off) = h; *(uint2*)(Kl + off) = l;
    }
    __syncthreads();

    float acc[4][4][4];
    #pragma unroll
    for (int i = 0; i < 4; i++)
        #pragma unroll
        for (int j = 0; j < 4; j++)
            #pragma unroll
            for (int e = 0; e < 4; e++) acc[i][j][e] = 0.0f;

    #pragma unroll
    for (int ks = 0; ks < 4; ks++) {
        uint32_t bhf[4][2], blf[4][2];
        #pragma unroll
        for (int in = 0; in < 4; in++) {
            int nrow = wn * 32 + in * 8 + (lane & 7);
            int cb = (ks * 16 + (lane & 8)) * 2;
            uint32_t off = SW128(nrow * 128 + cb);
            ldsm2(bhf[in][0], bhf[in][1], sKh + off);
            ldsm2(blf[in][0], blf[in][1], sKl + off);
        }
        #pragma unroll
        for (int im = 0; im < 4; im++) {
            int arow = wm * 64 + im * 16 + (lane & 15);
            int acb = (ks * 16 + ((lane >> 4) << 3)) * 2;
            uint32_t off = SW128(arow * 128 + acb);
            uint32_t ah[4], al[4];
            ldsm4(ah[0], ah[1], ah[2], ah[3], sQh + off);
            ldsm4(al[0], al[1], al[2], al[3], sQl + off);
            #pragma unroll
            for (int in = 0; in < 4; in++) {
                mmab(acc[im][in], ah, bhf[in]);
                mmab(acc[im][in], al, bhf[in]);
                mmab(acc[im][in], ah, blf[in]);
            }
        }
    }

    int b = bh >> 4;
    int g = lane >> 2, c2 = (lane & 3) * 2;
    #pragma unroll
    for (int im = 0; im < 4; im++)
        #pragma unroll
        for (int hh = 0; hh < 2; hh++) {
            int q = q0 + wm * 64 + im * 16 + g + hh * 8;
            float vals[8];
            #pragma unroll
            for (int in = 0; in < 4; in++) {
                int kc = k0 + wn * 32 + in * 8 + c2;
                unsigned short mk = *(const unsigned short*)&mask[(size_t)b * Sq * Sq + (size_t)q * Sq + kc];
                vals[in * 2]     = (mk & 0xffu) ? -1e9f : acc[im][in][hh * 2] * 0.125f;
                vals[in * 2 + 1] = ((mk >> 8) & 0xffu) ? -1e9f : acc[im][in][hh * 2 + 1] * 0.125f;
            }
            float m = vals[0];
            #pragma unroll
            for (int i = 1; i < 8; i++) m = fmaxf(m, vals[i]);
            m = fmaxf(m, __shfl_xor_sync(0xffffffffu, m, 1));
            m = fmaxf(m, __shfl_xor_sync(0xffffffffu, m, 2));
            float s = 0.0f;
            #pragma unroll
            for (int i = 0; i < 8; i++) s += __expf(vals[i] - m);
            s += __shfl_xor_sync(0xffffffffu, s, 1);
            s += __shfl_xor_sync(0xffffffffu, s, 2);
            if ((lane & 3) == 0)
                g_pstat[((size_t)bh * Sq + q) * 64 + blockIdx.x * 4 + wn] = make_float2(m, s);
        }
}

// ---------------- fold 64 partials per row -> rowmax, rinv ----------------
__global__ void __launch_bounds__(256) reduce_stats() {
    int r = blockIdx.x * 8 + (threadIdx.x >> 5);
    int lane = threadIdx.x & 31;
    float2 a = g_pstat[(size_t)r * 64 + lane];
    float2 b = g_pstat[(size_t)r * 64 + 32 + lane];
    float m = fmaxf(a.x, b.x);
    #pragma unroll
    for (int o = 16; o; o >>= 1) m = fmaxf(m, __shfl_xor_sync(0xffffffffu, m, o));
    float s = a.y * __expf(a.x - m) + b.y * __expf(b.x - m);
    #pragma unroll
    for (int o = 16; o; o >>= 1) s += __shfl_xor_sync(0xffffffffu, s, o);
    if (lane == 0) { g_rowmax[r] = m; g_rinv[r] = 1.0f / s; }
}

// ---------------- pass B: recompute QK^T, write probs, P@V via register fragments ----------------
// 256 thr / 8 warps; warp w owns q rows [w*16, w*16+16).
// smem: Qh 16K | Ql 16K | 2 stages x {Kh 8K, Kl 8K, Vh 8K, Vl 8K} = 96KB
__global__ void __launch_bounds__(256) fused_pv(const unsigned char* __restrict__ mask,
                                                float* __restrict__ attn) {
    extern __shared__ char smraw[];
    char* Qh = smraw;
    char* Ql = smraw + 16384;
    int t = threadIdx.x, lane = t & 31, w = t >> 5;
    int g = lane >> 2, c2 = (lane & 3) * 2;
    int bh = blockIdx.y, q0 = blockIdx.x * 128;
    size_t base = (size_t)bh * Sq * 64;   // g_Q/g_K/g_V head base
    uint32_t sQh = smaddr(Qh), sQl = smaddr(Ql);
    uint32_t sBase = smaddr(smraw);

    // load Q tile once (128 x 64)
    {
        int qr = t >> 1, qc = (t & 1) * 32;
        #pragma unroll
        for (int p = 0; p < 8; p++) {
            float4 qv = *(const float4*)&g_Q[base + (size_t)(q0 + qr) * 64 + qc + p * 4];
            uint2 h, l; split4(qv, h, l);
            uint32_t off = SW128(qr * 128 + (qc + p * 4) * 2);
            *(uint2*)(Qh + off) = h; *(uint2*)(Ql + off) = l;
        }
    }

    // per-thread rows + stats
    int qa = q0 + w * 16 + g, qb = qa + 8;
    float mxa = g_rowmax[bh * Sq + qa], ria = g_rinv[bh * Sq + qa];
    float mxb = g_rowmax[bh * Sq + qb], rib = g_rinv[bh * Sq + qb];
    size_t rowa = (size_t)bh * Sq * Sq + (size_t)qa * Sq;
    size_t rowb = (size_t)bh * Sq * Sq + (size_t)qb * Sq;
    const unsigned char* mrowa = mask + (size_t)(bh >> 4) * Sq * Sq + (size_t)qa * Sq;
    const unsigned char* mrowb = mask + (size_t)(bh >> 4) * Sq * Sq + (size_t)qb * Sq;

    float accc[8][4];
    #pragma unroll
    for (int j = 0; j < 8; j++)
        #pragma unroll
        for (int e = 0; e < 4; e++) accc[j][e] = 0.0f;

    // KV loaders
    int kr = t >> 2, kcf = (t & 3) * 16;
    float4 pk[4], pv[4];
    #pragma unroll
    for (int p = 0; p < 4; p++) {
        pk[p] = *(const float4*)&g_K[base + (size_t)kr * 64 + kcf + p * 4];
        pv[p] = *(const float4*)&g_V[base + (size_t)kr * 64 + kcf + p * 4];
    }

    for (int kt = 0; kt < 32; kt++) {
        int buf = kt & 1;
        char* Kh = smraw + 32768 + buf * 32768;
        char* Kl = Kh + 8192;
        char* Vh = Kh + 16384;
        char* Vl = Kh + 24576;
        #pragma unroll
        for (int p = 0; p < 4; p++) {
            uint2 h, l;
            split4(pk[p], h, l);
            uint32_t off = SW128(kr * 128 + (kcf + p * 4) * 2);
            *(uint2*)(Kh + off) = h; *(uint2*)(Kl + off) = l;
            split4(pv[p], h, l);
            *(uint2*)(Vh + off) = h; *(uint2*)(Vl + off) = l;
        }
        __syncthreads();
        if (kt < 31) {
            #pragma unroll
            for (int p = 0; p < 4; p++) {
                pk[p] = *(const float4*)&g_K[base + (size_t)((kt + 1) * 64 + kr) * 64 + kcf + p * 4];
                pv[p] = *(const float4*)&g_V[base + (size_t)((kt + 1) * 64 + kr) * 64 + kcf + p * 4];
            }
        }
        uint32_t sKh = sBase + 32768 + buf * 32768, sKl = sKh + 8192;
        uint32_t sVh = sKh + 16384, sVl = sKh + 24576;

        // ---- S = Q K^T for this 128q x 64k tile ----
        float accs[8][4];
        #pragma unroll
        for (int j = 0; j < 8; j++)
            #pragma unroll
            for (int e = 0; e < 4; e++) accs[j][e] = 0.0f;
        #pragma unroll
        for (int ks = 0; ks < 4; ks++) {
            int arow = w * 16 + (lane & 15);
            int acb = (ks * 16 + ((lane >> 4) << 3)) * 2;
            uint32_t offa = SW128(arow * 128 + acb);
            uint32_t ah[4], al[4];
            ldsm4(ah[0], ah[1], ah[2], ah[3], sQh + offa);
            ldsm4(al[0], al[1], al[2], al[3], sQl + offa);
            #pragma unroll
            for (int in = 0; in < 8; in++) {
                int nrow = in * 8 + (lane & 7);
                int cb = (ks * 16 + (lane & 8)) * 2;
                uint32_t off = SW128(nrow * 128 + cb);
                uint32_t bh0, bh1, bl0, bl1;
                ldsm2(bh0, bh1, sKh + off);
                ldsm2(bl0, bl1, sKl + off);
                uint32_t bhf[2] = {bh0, bh1}, blf[2] = {bl0, bl1};
                mmab(accs[in], ah, bhf);
                mmab(accs[in], al, bhf);
                mmab(accs[in], ah, blf);
            }
        }

        // ---- epilogue + PV per 16-k step ----
        #pragma unroll
        for (int ks = 0; ks < 4; ks++) {
            uint32_t ahp[4], alp[4];
            #pragma unroll
            for (int half = 0; half < 2; half++) {
                int in = 2 * ks + half;
                int kc = kt * 64 + in * 8 + c2;
                unsigned short mka = *(const unsigned short*)&mrowa[kc];
                unsigned short mkb = *(const unsigned short*)&mrowb[kc];
                float fa0 = (mka & 0xffu) ? -1e9f : accs[in][0] * 0.125f;
                float fa1 = ((mka >> 8) & 0xffu) ? -1e9f : accs[in][1] * 0.125f;
                float fb0 = (mkb & 0xffu) ? -1e9f : accs[in][2] * 0.125f;
                float fb1 = ((mkb >> 8) & 0xffu) ? -1e9f : accs[in][3] * 0.125f;
                float pa0 = __expf(fa0 - mxa) * ria;
                float pa1 = __expf(fa1 - mxa) * ria;
                float pb0 = __expf(fb0 - mxb) * rib;
                float pb1 = __expf(fb1 - mxb) * rib;
                *(float2*)&attn[rowa + kc] = make_float2(pa0, pa1);
                *(float2*)&attn[rowb + kc] = make_float2(pb0, pb1);
                pk2bf(pa0, pa1, ahp[half * 2], alp[half * 2]);         // a0/a2: row g
                pk2bf(pb0, pb1, ahp[half * 2 + 1], alp[half * 2 + 1]); // a1/a3: row g+8
            }
            #pragma unroll
            for (int jn = 0; jn < 8; jn++) {
                int krow = ks * 16 + (lane & 15);
                uint32_t off = SW128(krow * 128 + jn * 16);
                uint32_t bh0, bh1, bl0, bl1;
                ldsm2t(bh0, bh1, sVh + off);
                ldsm2t(bl0, bl1, sVl + off);
                uint32_t bvh[2] = {bh0, bh1}, bvl[2] = {bl0, bl1};
                mmab(accc[jn], ahp, bvh);
                mmab(accc[jn], alp, bvh);
                mmab(accc[jn], ahp, bvl);
            }
        }
    }

    int b = bh >> 4, h = bh & 15;
    #pragma unroll
    for (int jn = 0; jn < 8; jn++)
        #pragma unroll
        for (int hh = 0; hh < 2; hh++) {
            int q = q0 + w * 16 + g + hh * 8;
            int n = jn * 8 + c2;
            float2 v = make_float2(accc[jn][hh * 2], accc[jn][hh * 2 + 1]);
            *(float2*)&g_ctx[(size_t)(b * Sq + q) * 1024 + h * 64 + n] = v;
        }
}

// ---------------- residual + LayerNorm ----------------
__global__ void __launch_bounds__(256) ln_kernel(const float* __restrict__ inQ,
                                                 const float* __restrict__ gamma,
                                                 const float* __restrict__ beta,
                                                 float* __restrict__ out) {
    int m = blockIdx.x, t = threadIdx.x;
    size_t base = (size_t)m * 1024;
    float x[4];
    float s = 0.0f;
    #pragma unroll
    for (int i = 0; i < 4; i++) {
        int c = i * 256 + t;
        x[i] = g_proj[base + c] + inQ[base + c];
        s += x[i];
    }
    s = block_sum(s);
    float mu = s * (1.0f / 1024.0f);
    float s2 = 0.0f;
    #pragma unroll
    for (int i = 0; i < 4; i++) { float d = x[i] - mu; s2 += d * d; }
    s2 = block_sum(s2);
    float rstd = rsqrtf(s2 * (1.0f / 1024.0f) + 1e-5f);
    #pragma unroll
    for (int i = 0; i < 4; i++) {
        int c = i * 256 + t;
        out[base + c] = (x[i] - mu) * rstd * gamma[c] + beta[c];
    }
}

// ---------------- launch ----------------
extern "C" void kernel_launch(void* const* d_in, const int* in_sizes, int n_in,
                              void* d_out, int out_size) {
    const float* inQ = (const float*)d_in[0];
    const float* inK = (const float*)d_in[1];
    const float* inV = (const float*)d_in[2];
    const unsigned char* mask = (const unsigned char*)d_in[3];
    const float* wQ = (const float*)d_in[4];
    const float* wK = (const float*)d_in[5];
    const float* wV = (const float*)d_in[6];
    const float* wO = (const float*)d_in[7];
    const float* gamma = (const float*)d_in[8];
    const float* beta = (const float*)d_in[9];
    float* out = (float*)d_out;
    float* attn = out + (size_t)Bq * Sq * Eq;

    const int GEMM_SMEM = 131072;
    const int SC_SMEM   = 65536;
    const int FP_SMEM   = 98304;   // Q 32KB + 2 x 32KB KV stages
    cudaFuncSetAttribute(gemm8192, cudaFuncAttributeMaxDynamicSharedMemorySize, GEMM_SMEM);
    cudaFuncSetAttribute(scores_stats, cudaFuncAttributeMaxDynamicSharedMemorySize, SC_SMEM);
    cudaFuncSetAttribute(fused_pv, cudaFuncAttributeMaxDynamicSharedMemorySize, FP_SMEM);

    gemm8192<<<dim3(8, 64, 3), 256, GEMM_SMEM>>>(inQ, inK, inV, wQ, wK, wV, 0);
    scores_stats<<<dim3(16, 16, 64), 256, SC_SMEM>>>(mask);
    reduce_stats<<<Bq * Hq * Sq / 8, 256>>>();
    fused_pv<<<dim3(16, 64), 256, FP_SMEM>>>(mask, attn);
    gemm8192<<<dim3(8, 64, 1), 256, GEMM_SMEM>>>(nullptr, nullptr, nullptr, wO, nullptr, nullptr, 3);
    ln_kernel<<<Bq * Sq, 256>>>(inQ, gamma, beta, out);
}

// round 15
// speedup vs baseline: 2.1425x; 1.0639x over previous
#include <cuda_runtime.h>
#include <cuda_bf16.h>
#include <stdint.h>

#define Bq 4
#define Sq 2048
#define Eq 1024
#define Hq 16

#define SW128(o) ((o) ^ (((o) >> 3) & 0x70))
#define SW256(o) ((o) ^ (((o) >> 4) & 0x70))

// ---------------- scratch ----------------
__device__ __nv_bfloat16 g_Qh[(size_t)Bq*Hq*Sq*64];
__device__ __nv_bfloat16 g_Ql[(size_t)Bq*Hq*Sq*64];
__device__ __nv_bfloat16 g_Kh[(size_t)Bq*Hq*Sq*64];
__device__ __nv_bfloat16 g_Kl[(size_t)Bq*Hq*Sq*64];
__device__ __nv_bfloat16 g_Vh[(size_t)Bq*Hq*Sq*64];
__device__ __nv_bfloat16 g_Vl[(size_t)Bq*Hq*Sq*64];
__device__ float g_ctx[(size_t)Bq*Sq*Eq];
__device__ float g_proj[(size_t)Bq*Sq*Eq];
__device__ float g_rowmax[Bq*Hq*Sq];
__device__ float g_rinv[Bq*Hq*Sq];
__device__ float2 g_pstat[(size_t)Bq*Hq*Sq*64];

// ---------------- helpers ----------------
__device__ __forceinline__ void ldsm4(uint32_t& r0, uint32_t& r1, uint32_t& r2, uint32_t& r3, uint32_t a) {
    asm volatile("ldmatrix.sync.aligned.m8n8.x4.shared.b16 {%0,%1,%2,%3},[%4];"
                 : "=r"(r0), "=r"(r1), "=r"(r2), "=r"(r3) : "r"(a));
}
__device__ __forceinline__ void ldsm2(uint32_t& r0, uint32_t& r1, uint32_t a) {
    asm volatile("ldmatrix.sync.aligned.m8n8.x2.shared.b16 {%0,%1},[%2];"
                 : "=r"(r0), "=r"(r1) : "r"(a));
}
__device__ __forceinline__ void ldsm2t(uint32_t& r0, uint32_t& r1, uint32_t a) {
    asm volatile("ldmatrix.sync.aligned.m8n8.x2.trans.shared.b16 {%0,%1},[%2];"
                 : "=r"(r0), "=r"(r1) : "r"(a));
}
__device__ __forceinline__ void mmab(float* c, const uint32_t* a, const uint32_t* b) {
    asm volatile("mma.sync.aligned.m16n8k16.row.col.f32.bf16.bf16.f32 "
                 "{%0,%1,%2,%3},{%4,%5,%6,%7},{%8,%9},{%0,%1,%2,%3};"
                 : "+f"(c[0]), "+f"(c[1]), "+f"(c[2]), "+f"(c[3])
                 : "r"(a[0]), "r"(a[1]), "r"(a[2]), "r"(a[3]), "r"(b[0]), "r"(b[1]));
}
__device__ __forceinline__ uint32_t smaddr(const void* p) {
    return (uint32_t)__cvta_generic_to_shared(p);
}
__device__ __forceinline__ void split4(float4 v, uint2& h, uint2& l) {
    __nv_bfloat16 h0 = __float2bfloat16(v.x), h1 = __float2bfloat16(v.y);
    __nv_bfloat16 h2 = __float2bfloat16(v.z), h3 = __float2bfloat16(v.w);
    __nv_bfloat16 l0 = __float2bfloat16(v.x - __bfloat162float(h0));
    __nv_bfloat16 l1 = __float2bfloat16(v.y - __bfloat162float(h1));
    __nv_bfloat16 l2 = __float2bfloat16(v.z - __bfloat162float(h2));
    __nv_bfloat16 l3 = __float2bfloat16(v.w - __bfloat162float(h3));
    __nv_bfloat162 ph0(h0, h1), ph1(h2, h3), pl0(l0, l1), pl1(l2, l3);
    h.x = *(uint32_t*)&ph0; h.y = *(uint32_t*)&ph1;
    l.x = *(uint32_t*)&pl0; l.y = *(uint32_t*)&pl1;
}
__device__ __forceinline__ void pk2bf(float a, float b, uint32_t& h, uint32_t& l) {
    __nv_bfloat16 ha = __float2bfloat16(a), hb = __float2bfloat16(b);
    __nv_bfloat16 la = __float2bfloat16(a - __bfloat162float(ha));
    __nv_bfloat16 lb = __float2bfloat16(b - __bfloat162float(hb));
    __nv_bfloat162 ph(ha, hb), pl(la, lb);
    h = *(uint32_t*)&ph; l = *(uint32_t*)&pl;
}
__device__ __forceinline__ void cpasync16(uint32_t dst, const void* src) {
    asm volatile("cp.async.ca.shared.global [%0], [%1], 16;" :: "r"(dst), "l"(src));
}
__device__ __forceinline__ void cp_commit() { asm volatile("cp.async.commit_group;"); }
__device__ __forceinline__ void cp_wait0() { asm volatile("cp.async.wait_group 0;"); }

// ---------------- block reductions (ln kernel) ----------------
__device__ __forceinline__ float block_sum(float v) {
    __shared__ float sh[33];
    int lane = threadIdx.x & 31, w = threadIdx.x >> 5;
    #pragma unroll
    for (int o = 16; o; o >>= 1) v += __shfl_xor_sync(0xffffffffu, v, o);
    __syncthreads();
    if (lane == 0) sh[w] = v;
    __syncthreads();
    if (w == 0) {
        float x = (lane < 8) ? sh[lane] : 0.0f;
        #pragma unroll
        for (int o = 4; o; o >>= 1) x += __shfl_xor_sync(0xffffffffu, x, o);
        if (lane == 0) sh[32] = x;
    }
    __syncthreads();
    return sh[32];
}

// ---------------- projections / output GEMM (R7 pipeline) ----------------
__global__ void __launch_bounds__(256) gemm8192(const float* __restrict__ A0,
                                                const float* __restrict__ A1,
                                                const float* __restrict__ A2,
                                                const float* __restrict__ W0,
                                                const float* __restrict__ W1,
                                                const float* __restrict__ W2,
                                                int modeBase) {
    extern __shared__ char smraw[];
    int mode = modeBase + blockIdx.z;
    const float* Ap = (mode == 0) ? A0 : (mode == 1) ? A1 : (mode == 2) ? A2 : g_ctx;
    const float* W  = (mode == 1) ? W1 : (mode == 2) ? W2 : W0;
    int t = threadIdx.x, lane = t & 31, wid = t >> 5;
    int wm = wid >> 2, wn = wid & 3;
    int m0 = blockIdx.y * 128, n0 = blockIdx.x * 128;
    int ar = t >> 4, ac4 = (t & 15) * 4;
    int bk = t >> 5, bc4 = (t & 31) * 4;
    uint32_t sBase = smaddr(smraw);

    float4 pa[8], pb[8];
    float acc[4][4][4];
    #pragma unroll
    for (int i = 0; i < 4; i++)
        #pragma unroll
        for (int j = 0; j < 4; j++)
            #pragma unroll
            for (int e = 0; e < 4; e++) acc[i][j][e] = 0.0f;

    #pragma unroll
    for (int p = 0; p < 8; p++) {
        pa[p] = *(const float4*)&Ap[(size_t)(m0 + ar + 16 * p) * 1024 + ac4];
        pb[p] = *(const float4*)&W[(size_t)(bk + 8 * p) * 1024 + n0 + bc4];
    }

    for (int kt = 0; kt < 16; kt++) {
        int buf = kt & 1;
        char* Ah = smraw + buf * 65536;
        char* Al = Ah + 16384;
        char* Bh = Al + 16384;
        char* Bl = Bh + 16384;
        #pragma unroll
        for (int p = 0; p < 8; p++) {
            uint2 h, l;
            split4(pa[p], h, l);
            uint32_t off = SW128((ar + 16 * p) * 128 + ac4 * 2);
            *(uint2*)(Ah + off) = h; *(uint2*)(Al + off) = l;
            split4(pb[p], h, l);
            uint32_t offb = SW256((bk + 8 * p) * 256 + bc4 * 2);
            *(uint2*)(Bh + offb) = h; *(uint2*)(Bl + offb) = l;
        }
        __syncthreads();
        if (kt < 15) {
            #pragma unroll
            for (int p = 0; p < 8; p++) {
                pa[p] = *(const float4*)&Ap[(size_t)(m0 + ar + 16 * p) * 1024 + (kt + 1) * 64 + ac4];
                pb[p] = *(const float4*)&W[(size_t)((kt + 1) * 64 + bk + 8 * p) * 1024 + n0 + bc4];
            }
        }
        uint32_t sAh = sBase + buf * 65536, sAl = sAh + 16384;
        uint32_t sBh = sAl + 16384, sBl = sBh + 16384;
        #pragma unroll
        for (int ks = 0; ks < 4; ks++) {
            uint32_t bhf[4][2], blf[4][2];
            #pragma unroll
            for (int in = 0; in < 4; in++) {
                int krow = ks * 16 + (lane & 15);
                int nb = (wn * 32 + in * 8) * 2;
                uint32_t off = SW256(krow * 256 + nb);
                ldsm2t(bhf[in][0], bhf[in][1], sBh + off);
                ldsm2t(blf[in][0], blf[in][1], sBl + off);
            }
            #pragma unroll
            for (int im = 0; im < 4; im++) {
                int arow = wm * 64 + im * 16 + (lane & 15);
                int acb = (ks * 16 + ((lane >> 4) << 3)) * 2;
                uint32_t off = SW128(arow * 128 + acb);
                uint32_t ah[4], al[4];
                ldsm4(ah[0], ah[1], ah[2], ah[3], sAh + off);
                ldsm4(al[0], al[1], al[2], al[3], sAl + off);
                #pragma unroll
                for (int in = 0; in < 4; in++) {
                    mmab(acc[im][in], ah, bhf[in]);
                    mmab(acc[im][in], al, bhf[in]);
                    mmab(acc[im][in], ah, blf[in]);
                }
            }
        }
    }

    int g = lane >> 2, c2 = (lane & 3) * 2;
    #pragma unroll
    for (int im = 0; im < 4; im++)
        #pragma unroll
        for (int in = 0; in < 4; in++)
            #pragma unroll
            for (int hh = 0; hh < 2; hh++) {
                int m = m0 + wm * 64 + im * 16 + g + hh * 8;
                int n = n0 + wn * 32 + in * 8 + c2;
                float2 v = make_float2(acc[im][in][hh * 2], acc[im][in][hh * 2 + 1]);
                if (mode <= 2) {
                    __nv_bfloat16* Oh = (mode == 0) ? g_Qh : (mode == 1) ? g_Kh : g_Vh;
                    __nv_bfloat16* Ol = (mode == 0) ? g_Ql : (mode == 1) ? g_Kl : g_Vl;
                    int b = m >> 11, s = m & 2047;
                    int h = n >> 6, d = n & 63;
                    size_t idx = ((size_t)(b * Hq + h) * Sq + s) * 64 + d;
                    uint32_t hb, lb; pk2bf(v.x, v.y, hb, lb);
                    *(uint32_t*)&Oh[idx] = hb;
                    *(uint32_t*)&Ol[idx] = lb;
                } else {
                    *(float2*)&g_proj[(size_t)m * 1024 + n] = v;
                }
            }
}

// ---------------- pass A: stats-only scores ----------------
__global__ void __launch_bounds__(256, 2) scores_stats(const unsigned char* __restrict__ mask) {
    extern __shared__ char smraw[];
    char* Qh = smraw;
    char* Ql = Qh + 16384;
    char* Kh = Ql + 16384;
    char* Kl = Kh + 16384;
    int t = threadIdx.x, lane = t & 31, wid = t >> 5;
    int wm = wid >> 2, wn = wid & 3;
    int bh = blockIdx.z, q0 = blockIdx.y * 128, k0 = blockIdx.x * 128;
    size_t base = (size_t)bh * Sq * 64;
    uint32_t sQh = smaddr(Qh), sQl = smaddr(Ql), sKh = smaddr(Kh), sKl = smaddr(Kl);

    #pragma unroll
    for (int p = 0; p < 8; p++) {
        int r = (t >> 4) + 16 * p, c4 = (t & 15) * 4;
        uint32_t off = SW128(r * 128 + c4 * 2);
        size_t qi = base + (size_t)(q0 + r) * 64 + c4;
        size_t ki = base + (size_t)(k0 + r) * 64 + c4;
        *(uint2*)(Qh + off) = *(const uint2*)&g_Qh[qi];
        *(uint2*)(Ql + off) = *(const uint2*)&g_Ql[qi];
        *(uint2*)(Kh + off) = *(const uint2*)&g_Kh[ki];
        *(uint2*)(Kl + off) = *(const uint2*)&g_Kl[ki];
    }
    __syncthreads();

    float acc[4][4][4];
    #pragma unroll
    for (int i = 0; i < 4; i++)
        #pragma unroll
        for (int j = 0; j < 4; j++)
            #pragma unroll
            for (int e = 0; e < 4; e++) acc[i][j][e] = 0.0f;

    #pragma unroll
    for (int ks = 0; ks < 4; ks++) {
        uint32_t bhf[4][2], blf[4][2];
        #pragma unroll
        for (int in = 0; in < 4; in++) {
            int nrow = wn * 32 + in * 8 + (lane & 7);
            int cb = (ks * 16 + (lane & 8)) * 2;
            uint32_t off = SW128(nrow * 128 + cb);
            ldsm2(bhf[in][0], bhf[in][1], sKh + off);
            ldsm2(blf[in][0], blf[in][1], sKl + off);
        }
        #pragma unroll
        for (int im = 0; im < 4; im++) {
            int arow = wm * 64 + im * 16 + (lane & 15);
            int acb = (ks * 16 + ((lane >> 4) << 3)) * 2;
            uint32_t off = SW128(arow * 128 + acb);
            uint32_t ah[4], al[4];
            ldsm4(ah[0], ah[1], ah[2], ah[3], sQh + off);
            ldsm4(al[0], al[1], al[2], al[3], sQl + off);
            #pragma unroll
            for (int in = 0; in < 4; in++) {
                mmab(acc[im][in], ah, bhf[in]);
                mmab(acc[im][in], al, bhf[in]);
                mmab(acc[im][in], ah, blf[in]);
            }
        }
    }

    int b = bh >> 4;
    int g = lane >> 2, c2 = (lane & 3) * 2;
    #pragma unroll
    for (int im = 0; im < 4; im++)
        #pragma unroll
        for (int hh = 0; hh < 2; hh++) {
            int q = q0 + wm * 64 + im * 16 + g + hh * 8;
            float vals[8];
            #pragma unroll
            for (int in = 0; in < 4; in++) {
                int kc = k0 + wn * 32 + in * 8 + c2;
                unsigned short mk = *(const unsigned short*)&mask[(size_t)b * Sq * Sq + (size_t)q * Sq + kc];
                vals[in * 2]     = (mk & 0xffu) ? -1e9f : acc[im][in][hh * 2] * 0.125f;
                vals[in * 2 + 1] = ((mk >> 8) & 0xffu) ? -1e9f : acc[im][in][hh * 2 + 1] * 0.125f;
            }
            float m = vals[0];
            #pragma unroll
            for (int i = 1; i < 8; i++) m = fmaxf(m, vals[i]);
            m = fmaxf(m, __shfl_xor_sync(0xffffffffu, m, 1));
            m = fmaxf(m, __shfl_xor_sync(0xffffffffu, m, 2));
            float s = 0.0f;
            #pragma unroll
            for (int i = 0; i < 8; i++) s += __expf(vals[i] - m);
            s += __shfl_xor_sync(0xffffffffu, s, 1);
            s += __shfl_xor_sync(0xffffffffu, s, 2);
            if ((lane & 3) == 0)
                g_pstat[((size_t)bh * Sq + q) * 64 + blockIdx.x * 4 + wn] = make_float2(m, s);
        }
}

// ---------------- fold 64 partials per row -> rowmax, rinv ----------------
__global__ void __launch_bounds__(256) reduce_stats() {
    int r = blockIdx.x * 8 + (threadIdx.x >> 5);
    int lane = threadIdx.x & 31;
    float2 a = g_pstat[(size_t)r * 64 + lane];
    float2 b = g_pstat[(size_t)r * 64 + 32 + lane];
    float m = fmaxf(a.x, b.x);
    #pragma unroll
    for (int o = 16; o; o >>= 1) m = fmaxf(m, __shfl_xor_sync(0xffffffffu, m, o));
    float s = a.y * __expf(a.x - m) + b.y * __expf(b.x - m);
    #pragma unroll
    for (int o = 16; o; o >>= 1) s += __shfl_xor_sync(0xffffffffu, s, o);
    if (lane == 0) { g_rowmax[r] = m; g_rinv[r] = 1.0f / s; }
}

// ---------------- pass B: recompute QK^T, write probs, P@V (cp.async staged K/V) ----------------
// smem: Qh 16K | Ql 16K | 2 stages x {Kh 8K | Kl 8K | Vh 8K | Vl 8K} = 96KB
__global__ void __launch_bounds__(256, 2) fused_pv(const unsigned char* __restrict__ mask,
                                                   float* __restrict__ attn) {
    extern __shared__ char smraw[];
    int t = threadIdx.x, lane = t & 31, w = t >> 5;
    int g = lane >> 2, c2 = (lane & 3) * 2;
    int bh = blockIdx.y, q0 = blockIdx.x * 128;
    size_t base = (size_t)bh * Sq * 64;
    uint32_t sBase = smaddr(smraw);
    uint32_t sQh = sBase, sQl = sBase + 16384;

    // Q tile staging (one-time)
    {
        int qr = t >> 1, qc = (t & 1) * 32;
        #pragma unroll
        for (int p = 0; p < 4; p++) {
            size_t qi = base + (size_t)(q0 + qr) * 64 + qc + p * 8;
            uint32_t off = SW128(qr * 128 + (qc + p * 8) * 2);
            *(uint4*)(smraw + off) = *(const uint4*)&g_Qh[qi];
            *(uint4*)(smraw + 16384 + off) = *(const uint4*)&g_Ql[qi];
        }
    }

    // K/V staging geometry: 64 rows x 128 bytes per plane; 4 thr/row, 32 B (2 chunks) each
    int kr = t >> 2, kc = (t & 3) * 16;                 // element offset (16 bf16 = 32 B)
    uint32_t soff0 = SW128(kr * 128 + kc * 2);
    uint32_t soff1 = SW128(kr * 128 + kc * 2 + 16);
    {
        uint32_t s0 = sBase + 32768;
        size_t gi = base + (size_t)kr * 64 + kc;
        cpasync16(s0 + soff0,         &g_Kh[gi]);     cpasync16(s0 + soff1,         &g_Kh[gi + 8]);
        cpasync16(s0 + 8192 + soff0,  &g_Kl[gi]);     cpasync16(s0 + 8192 + soff1,  &g_Kl[gi + 8]);
        cpasync16(s0 + 16384 + soff0, &g_Vh[gi]);     cpasync16(s0 + 16384 + soff1, &g_Vh[gi + 8]);
        cpasync16(s0 + 24576 + soff0, &g_Vl[gi]);     cpasync16(s0 + 24576 + soff1, &g_Vl[gi + 8]);
        cp_commit();
    }

    int qa = q0 + w * 16 + g, qb = qa + 8;
    float mxa = g_rowmax[bh * Sq + qa], ria = g_rinv[bh * Sq + qa];
    float mxb = g_rowmax[bh * Sq + qb], rib = g_rinv[bh * Sq + qb];
    size_t rowa = (size_t)bh * Sq * Sq + (size_t)qa * Sq;
    size_t rowb = (size_t)bh * Sq * Sq + (size_t)qb * Sq;
    const unsigned char* mrowa = mask + (size_t)(bh >> 4) * Sq * Sq + (size_t)qa * Sq;
    const unsigned char* mrowb = mask + (size_t)(bh >> 4) * Sq * Sq + (size_t)qb * Sq;

    float accc[8][4];
    #pragma unroll
    for (int j = 0; j < 8; j++)
        #pragma unroll
        for (int e = 0; e < 4; e++) accc[j][e] = 0.0f;

    for (int kt = 0; kt < 32; kt++) {
        int buf = kt & 1;
        cp_wait0();
        __syncthreads();
        if (kt < 31) {
            uint32_t sn = sBase + 32768 + (buf ^ 1) * 32768;
            size_t gi = base + (size_t)((kt + 1) * 64 + kr) * 64 + kc;
            cpasync16(sn + soff0,         &g_Kh[gi]);     cpasync16(sn + soff1,         &g_Kh[gi + 8]);
            cpasync16(sn + 8192 + soff0,  &g_Kl[gi]);     cpasync16(sn + 8192 + soff1,  &g_Kl[gi + 8]);
            cpasync16(sn + 16384 + soff0, &g_Vh[gi]);     cpasync16(sn + 16384 + soff1, &g_Vh[gi + 8]);
            cpasync16(sn + 24576 + soff0, &g_Vl[gi]);     cpasync16(sn + 24576 + soff1, &g_Vl[gi + 8]);
            cp_commit();
        }
        uint32_t sKh = sBase + 32768 + buf * 32768, sKl = sKh + 8192;
        uint32_t sVh = sKh + 16384, sVl = sKh + 24576;

        // ---- S = Q K^T for this 128q x 64k tile ----
        float accs[8][4];
        #pragma unroll
        for (int j = 0; j < 8; j++)
            #pragma unroll
            for (int e = 0; e < 4; e++) accs[j][e] = 0.0f;
        #pragma unroll
        for (int ks = 0; ks < 4; ks++) {
            int arow = w * 16 + (lane & 15);
            int acb = (ks * 16 + ((lane >> 4) << 3)) * 2;
            uint32_t offa = SW128(arow * 128 + acb);
            uint32_t ah[4], al[4];
            ldsm4(ah[0], ah[1], ah[2], ah[3], sQh + offa);
            ldsm4(al[0], al[1], al[2], al[3], sQl + offa);
            #pragma unroll
            for (int in = 0; in < 8; in++) {
                int nrow = in * 8 + (lane & 7);
                int cb = (ks * 16 + (lane & 8)) * 2;
                uint32_t off = SW128(nrow * 128 + cb);
                uint32_t bh0, bh1, bl0, bl1;
                ldsm2(bh0, bh1, sKh + off);
                ldsm2(bl0, bl1, sKl + off);
                uint32_t bhf[2] = {bh0, bh1}, blf[2] = {bl0, bl1};
                mmab(accs[in], ah, bhf);
                mmab(accs[in], al, bhf);
                mmab(accs[in], ah, blf);
            }
        }

        // ---- epilogue + PV per 16-k step ----
        #pragma unroll
        for (int ks = 0; ks < 4; ks++) {
            uint32_t ahp[4], alp[4];
            #pragma unroll
            for (int half = 0; half < 2; half++) {
                int in = 2 * ks + half;
                int kcol = kt * 64 + in * 8 + c2;
                unsigned short mka = *(const unsigned short*)&mrowa[kcol];
                unsigned short mkb = *(const unsigned short*)&mrowb[kcol];
                float fa0 = (mka & 0xffu) ? -1e9f : accs[in][0] * 0.125f;
                float fa1 = ((mka >> 8) & 0xffu) ? -1e9f : accs[in][1] * 0.125f;
                float fb0 = (mkb & 0xffu) ? -1e9f : accs[in][2] * 0.125f;
                float fb1 = ((mkb >> 8) & 0xffu) ? -1e9f : accs[in][3] * 0.125f;
                float pa0 = __expf(fa0 - mxa) * ria;
                float pa1 = __expf(fa1 - mxa) * ria;
                float pb0 = __expf(fb0 - mxb) * rib;
                float pb1 = __expf(fb1 - mxb) * rib;
                *(float2*)&attn[rowa + kcol] = make_float2(pa0, pa1);
                *(float2*)&attn[rowb + kcol] = make_float2(pb0, pb1);
                pk2bf(pa0, pa1, ahp[half * 2], alp[half * 2]);
                pk2bf(pb0, pb1, ahp[half * 2 + 1], alp[half * 2 + 1]);
            }
            #pragma unroll
            for (int jn = 0; jn < 8; jn++) {
                int krow = ks * 16 + (lane & 15);
                uint32_t off = SW128(krow * 128 + jn * 16);
                uint32_t bh0, bh1, bl0, bl1;
                ldsm2t(bh0, bh1, sVh + off);
                ldsm2t(bl0, bl1, sVl + off);
                uint32_t bvh[2] = {bh0, bh1}, bvl[2] = {bl0, bl1};
                mmab(accc[jn], ahp, bvh);
                mmab(accc[jn], alp, bvh);
                mmab(accc[jn], ahp, bvl);
            }
        }
    }

    int b = bh >> 4, h = bh & 15;
    #pragma unroll
    for (int jn = 0; jn < 8; jn++)
        #pragma unroll
        for (int hh = 0; hh < 2; hh++) {
            int q = q0 + w * 16 + g + hh * 8;
            int n = jn * 8 + c2;
            float2 v = make_float2(accc[jn][hh * 2], accc[jn][hh * 2 + 1]);
            *(float2*)&g_ctx[(size_t)(b * Sq + q) * 1024 + h * 64 + n] = v;
        }
}

// ---------------- residual + LayerNorm ----------------
__global__ void __launch_bounds__(256) ln_kernel(const float* __restrict__ inQ,
                                                 const float* __restrict__ gamma,
                                                 const float* __restrict__ beta,
                                                 float* __restrict__ out) {
    int m = blockIdx.x, t = threadIdx.x;
    size_t base = (size_t)m * 1024;
    float x[4];
    float s = 0.0f;
    #pragma unroll
    for (int i = 0; i < 4; i++) {
        int c = i * 256 + t;
        x[i] = g_proj[base + c] + inQ[base + c];
        s += x[i];
    }
    s = block_sum(s);
    float mu = s * (1.0f / 1024.0f);
    float s2 = 0.0f;
    #pragma unroll
    for (int i = 0; i < 4; i++) { float d = x[i] - mu; s2 += d * d; }
    s2 = block_sum(s2);
    float rstd = rsqrtf(s2 * (1.0f / 1024.0f) + 1e-5f);
    #pragma unroll
    for (int i = 0; i < 4; i++) {
        int c = i * 256 + t;
        out[base + c] = (x[i] - mu) * rstd * gamma[c] + beta[c];
    }
}

// ---------------- launch ----------------
extern "C" void kernel_launch(void* const* d_in, const int* in_sizes, int n_in,
                              void* d_out, int out_size) {
    const float* inQ = (const float*)d_in[0];
    const float* inK = (const float*)d_in[1];
    const float* inV = (const float*)d_in[2];
    const unsigned char* mask = (const unsigned char*)d_in[3];
    const float* wQ = (const float*)d_in[4];
    const float* wK = (const float*)d_in[5];
    const float* wV = (const float*)d_in[6];
    const float* wO = (const float*)d_in[7];
    const float* gamma = (const float*)d_in[8];
    const float* beta = (const float*)d_in[9];
    float* out = (float*)d_out;
    float* attn = out + (size_t)Bq * Sq * Eq;

    const int GEMM_SMEM = 131072;
    const int SC_SMEM   = 65536;
    const int FP_SMEM   = 98304;
    cudaFuncSetAttribute(gemm8192, cudaFuncAttributeMaxDynamicSharedMemorySize, GEMM_SMEM);
    cudaFuncSetAttribute(scores_stats, cudaFuncAttributeMaxDynamicSharedMemorySize, SC_SMEM);
    cudaFuncSetAttribute(fused_pv, cudaFuncAttributeMaxDynamicSharedMemorySize, FP_SMEM);

    gemm8192<<<dim3(8, 64, 3), 256, GEMM_SMEM>>>(inQ, inK, inV, wQ, wK, wV, 0);
    scores_stats<<<dim3(16, 16, 64), 256, SC_SMEM>>>(mask);
    reduce_stats<<<Bq * Hq * Sq / 8, 256>>>();
    fused_pv<<<dim3(16, 64), 256, FP_SMEM>>>(mask, attn);
    gemm8192<<<dim3(8, 64, 1), 256, GEMM_SMEM>>>(nullptr, nullptr, nullptr, wO, nullptr, nullptr, 3);
    ln_kernel<<<Bq * Sq, 256>>>(inQ, gamma, beta, out);
}

// round 16
// speedup vs baseline: 2.2993x; 1.0732x over previous
#include <cuda_runtime.h>
#include <cuda_bf16.h>
#include <stdint.h>

#define Bq 4
#define Sq 2048
#define Eq 1024
#define Hq 16

#define SW128(o) ((o) ^ (((o) >> 3) & 0x70))
#define SW256(o) ((o) ^ (((o) >> 4) & 0x70))

// ---------------- scratch ----------------
__device__ __nv_bfloat16 g_Qh[(size_t)Bq*Hq*Sq*64];
__device__ __nv_bfloat16 g_Ql[(size_t)Bq*Hq*Sq*64];
__device__ __nv_bfloat16 g_Kh[(size_t)Bq*Hq*Sq*64];
__device__ __nv_bfloat16 g_Kl[(size_t)Bq*Hq*Sq*64];
__device__ __nv_bfloat16 g_Vh[(size_t)Bq*Hq*Sq*64];
__device__ __nv_bfloat16 g_Vl[(size_t)Bq*Hq*Sq*64];
__device__ float g_ctx[(size_t)Bq*Sq*Eq];
__device__ float g_proj[(size_t)Bq*Sq*Eq];
__device__ float g_rowmax[Bq*Hq*Sq];
__device__ float g_rinv[Bq*Hq*Sq];
__device__ float2 g_pstat[(size_t)Bq*Hq*Sq*64];

// ---------------- helpers ----------------
__device__ __forceinline__ void ldsm4(uint32_t& r0, uint32_t& r1, uint32_t& r2, uint32_t& r3, uint32_t a) {
    asm volatile("ldmatrix.sync.aligned.m8n8.x4.shared.b16 {%0,%1,%2,%3},[%4];"
                 : "=r"(r0), "=r"(r1), "=r"(r2), "=r"(r3) : "r"(a));
}
__device__ __forceinline__ void ldsm4t(uint32_t& r0, uint32_t& r1, uint32_t& r2, uint32_t& r3, uint32_t a) {
    asm volatile("ldmatrix.sync.aligned.m8n8.x4.trans.shared.b16 {%0,%1,%2,%3},[%4];"
                 : "=r"(r0), "=r"(r1), "=r"(r2), "=r"(r3) : "r"(a));
}
__device__ __forceinline__ void mmab(float* c, const uint32_t* a, const uint32_t* b) {
    asm volatile("mma.sync.aligned.m16n8k16.row.col.f32.bf16.bf16.f32 "
                 "{%0,%1,%2,%3},{%4,%5,%6,%7},{%8,%9},{%0,%1,%2,%3};"
                 : "+f"(c[0]), "+f"(c[1]), "+f"(c[2]), "+f"(c[3])
                 : "r"(a[0]), "r"(a[1]), "r"(a[2]), "r"(a[3]), "r"(b[0]), "r"(b[1]));
}
__device__ __forceinline__ uint32_t smaddr(const void* p) {
    return (uint32_t)__cvta_generic_to_shared(p);
}
__device__ __forceinline__ void split4(float4 v, uint2& h, uint2& l) {
    __nv_bfloat16 h0 = __float2bfloat16(v.x), h1 = __float2bfloat16(v.y);
    __nv_bfloat16 h2 = __float2bfloat16(v.z), h3 = __float2bfloat16(v.w);
    __nv_bfloat16 l0 = __float2bfloat16(v.x - __bfloat162float(h0));
    __nv_bfloat16 l1 = __float2bfloat16(v.y - __bfloat162float(h1));
    __nv_bfloat16 l2 = __float2bfloat16(v.z - __bfloat162float(h2));
    __nv_bfloat16 l3 = __float2bfloat16(v.w - __bfloat162float(h3));
    __nv_bfloat162 ph0(h0, h1), ph1(h2, h3), pl0(l0, l1), pl1(l2, l3);
    h.x = *(uint32_t*)&ph0; h.y = *(uint32_t*)&ph1;
    l.x = *(uint32_t*)&pl0; l.y = *(uint32_t*)&pl1;
}
__device__ __forceinline__ void pk2bf(float a, float b, uint32_t& h, uint32_t& l) {
    __nv_bfloat16 ha = __float2bfloat16(a), hb = __float2bfloat16(b);
    __nv_bfloat16 la = __float2bfloat16(a - __bfloat162float(ha));
    __nv_bfloat16 lb = __float2bfloat16(b - __bfloat162float(hb));
    __nv_bfloat162 ph(ha, hb), pl(la, lb);
    h = *(uint32_t*)&ph; l = *(uint32_t*)&pl;
}
__device__ __forceinline__ void cpasync16(uint32_t dst, const void* src) {
    asm volatile("cp.async.ca.shared.global [%0], [%1], 16;" :: "r"(dst), "l"(src));
}
__device__ __forceinline__ void cp_commit() { asm volatile("cp.async.commit_group;"); }
__device__ __forceinline__ void cp_wait0() { asm volatile("cp.async.wait_group 0;"); }

// ---------------- block reductions (ln kernel) ----------------
__device__ __forceinline__ float block_sum(float v) {
    __shared__ float sh[33];
    int lane = threadIdx.x & 31, w = threadIdx.x >> 5;
    #pragma unroll
    for (int o = 16; o; o >>= 1) v += __shfl_xor_sync(0xffffffffu, v, o);
    __syncthreads();
    if (lane == 0) sh[w] = v;
    __syncthreads();
    if (w == 0) {
        float x = (lane < 8) ? sh[lane] : 0.0f;
        #pragma unroll
        for (int o = 4; o; o >>= 1) x += __shfl_xor_sync(0xffffffffu, x, o);
        if (lane == 0) sh[32] = x;
    }
    __syncthreads();
    return sh[32];
}

// ---------------- projections / output GEMM (R7 pipeline, x4 B-loads) ----------------
__global__ void __launch_bounds__(256) gemm8192(const float* __restrict__ A0,
                                                const float* __restrict__ A1,
                                                const float* __restrict__ A2,
                                                const float* __restrict__ W0,
                                                const float* __restrict__ W1,
                                                const float* __restrict__ W2,
                                                int modeBase) {
    extern __shared__ char smraw[];
    int mode = modeBase + blockIdx.z;
    const float* Ap = (mode == 0) ? A0 : (mode == 1) ? A1 : (mode == 2) ? A2 : g_ctx;
    const float* W  = (mode == 1) ? W1 : (mode == 2) ? W2 : W0;
    int t = threadIdx.x, lane = t & 31, wid = t >> 5;
    int wm = wid >> 2, wn = wid & 3;
    int m0 = blockIdx.y * 128, n0 = blockIdx.x * 128;
    int ar = t >> 4, ac4 = (t & 15) * 4;
    int bk = t >> 5, bc4 = (t & 31) * 4;
    uint32_t sBase = smaddr(smraw);

    float4 pa[8], pb[8];
    float acc[4][4][4];
    #pragma unroll
    for (int i = 0; i < 4; i++)
        #pragma unroll
        for (int j = 0; j < 4; j++)
            #pragma unroll
            for (int e = 0; e < 4; e++) acc[i][j][e] = 0.0f;

    #pragma unroll
    for (int p = 0; p < 8; p++) {
        pa[p] = *(const float4*)&Ap[(size_t)(m0 + ar + 16 * p) * 1024 + ac4];
        pb[p] = *(const float4*)&W[(size_t)(bk + 8 * p) * 1024 + n0 + bc4];
    }

    for (int kt = 0; kt < 16; kt++) {
        int buf = kt & 1;
        char* Ah = smraw + buf * 65536;
        char* Al = Ah + 16384;
        char* Bh = Al + 16384;
        char* Bl = Bh + 16384;
        #pragma unroll
        for (int p = 0; p < 8; p++) {
            uint2 h, l;
            split4(pa[p], h, l);
            uint32_t off = SW128((ar + 16 * p) * 128 + ac4 * 2);
            *(uint2*)(Ah + off) = h; *(uint2*)(Al + off) = l;
            split4(pb[p], h, l);
            uint32_t offb = SW256((bk + 8 * p) * 256 + bc4 * 2);
            *(uint2*)(Bh + offb) = h; *(uint2*)(Bl + offb) = l;
        }
        __syncthreads();
        if (kt < 15) {
            #pragma unroll
            for (int p = 0; p < 8; p++) {
                pa[p] = *(const float4*)&Ap[(size_t)(m0 + ar + 16 * p) * 1024 + (kt + 1) * 64 + ac4];
                pb[p] = *(const float4*)&W[(size_t)((kt + 1) * 64 + bk + 8 * p) * 1024 + n0 + bc4];
            }
        }
        uint32_t sAh = sBase + buf * 65536, sAl = sAh + 16384;
        uint32_t sBh = sAl + 16384, sBl = sBh + 16384;
        #pragma unroll
        for (int ks = 0; ks < 4; ks++) {
            uint32_t bhf[4][2], blf[4][2];
            #pragma unroll
            for (int in2 = 0; in2 < 4; in2 += 2) {
                int krow = ks * 16 + (lane & 15);
                int nb = (wn * 32 + (in2 + (lane >> 4)) * 8) * 2;
                uint32_t off = SW256(krow * 256 + nb);
                ldsm4t(bhf[in2][0], bhf[in2][1], bhf[in2 + 1][0], bhf[in2 + 1][1], sBh + off);
                ldsm4t(blf[in2][0], blf[in2][1], blf[in2 + 1][0], blf[in2 + 1][1], sBl + off);
            }
            #pragma unroll
            for (int im = 0; im < 4; im++) {
                int arow = wm * 64 + im * 16 + (lane & 15);
                int acb = (ks * 16 + ((lane >> 4) << 3)) * 2;
                uint32_t off = SW128(arow * 128 + acb);
                uint32_t ah[4], al[4];
                ldsm4(ah[0], ah[1], ah[2], ah[3], sAh + off);
                ldsm4(al[0], al[1], al[2], al[3], sAl + off);
                #pragma unroll
                for (int in = 0; in < 4; in++) {
                    mmab(acc[im][in], ah, bhf[in]);
                    mmab(acc[im][in], al, bhf[in]);
                    mmab(acc[im][in], ah, blf[in]);
                }
            }
        }
    }

    int g = lane >> 2, c2 = (lane & 3) * 2;
    #pragma unroll
    for (int im = 0; im < 4; im++)
        #pragma unroll
        for (int in = 0; in < 4; in++)
            #pragma unroll
            for (int hh = 0; hh < 2; hh++) {
                int m = m0 + wm * 64 + im * 16 + g + hh * 8;
                int n = n0 + wn * 32 + in * 8 + c2;
                float2 v = make_float2(acc[im][in][hh * 2], acc[im][in][hh * 2 + 1]);
                if (mode <= 2) {
                    __nv_bfloat16* Oh = (mode == 0) ? g_Qh : (mode == 1) ? g_Kh : g_Vh;
                    __nv_bfloat16* Ol = (mode == 0) ? g_Ql : (mode == 1) ? g_Kl : g_Vl;
                    int b = m >> 11, s = m & 2047;
                    int h = n >> 6, d = n & 63;
                    size_t idx = ((size_t)(b * Hq + h) * Sq + s) * 64 + d;
                    uint32_t hb, lb; pk2bf(v.x, v.y, hb, lb);
                    *(uint32_t*)&Oh[idx] = hb;
                    *(uint32_t*)&Ol[idx] = lb;
                } else {
                    *(float2*)&g_proj[(size_t)m * 1024 + n] = v;
                }
            }
}

// ---------------- pass A: stats-only scores (x4 K loads) ----------------
__global__ void __launch_bounds__(256, 2) scores_stats(const unsigned char* __restrict__ mask) {
    extern __shared__ char smraw[];
    char* Qh = smraw;
    char* Ql = Qh + 16384;
    char* Kh = Ql + 16384;
    char* Kl = Kh + 16384;
    int t = threadIdx.x, lane = t & 31, wid = t >> 5;
    int wm = wid >> 2, wn = wid & 3;
    int bh = blockIdx.z, q0 = blockIdx.y * 128, k0 = blockIdx.x * 128;
    size_t base = (size_t)bh * Sq * 64;
    uint32_t sQh = smaddr(Qh), sQl = smaddr(Ql), sKh = smaddr(Kh), sKl = smaddr(Kl);

    #pragma unroll
    for (int p = 0; p < 8; p++) {
        int r = (t >> 4) + 16 * p, c4 = (t & 15) * 4;
        uint32_t off = SW128(r * 128 + c4 * 2);
        size_t qi = base + (size_t)(q0 + r) * 64 + c4;
        size_t ki = base + (size_t)(k0 + r) * 64 + c4;
        *(uint2*)(Qh + off) = *(const uint2*)&g_Qh[qi];
        *(uint2*)(Ql + off) = *(const uint2*)&g_Ql[qi];
        *(uint2*)(Kh + off) = *(const uint2*)&g_Kh[ki];
        *(uint2*)(Kl + off) = *(const uint2*)&g_Kl[ki];
    }
    __syncthreads();

    float acc[4][4][4];
    #pragma unroll
    for (int i = 0; i < 4; i++)
        #pragma unroll
        for (int j = 0; j < 4; j++)
            #pragma unroll
            for (int e = 0; e < 4; e++) acc[i][j][e] = 0.0f;

    #pragma unroll
    for (int ks = 0; ks < 4; ks++) {
        uint32_t bhf[4][2], blf[4][2];
        #pragma unroll
        for (int in2 = 0; in2 < 4; in2 += 2) {
            int nrow = wn * 32 + (in2 + (lane >> 4)) * 8 + (lane & 7);
            int cb = (ks * 16 + (lane & 8)) * 2;
            uint32_t off = SW128(nrow * 128 + cb);
            ldsm4(bhf[in2][0], bhf[in2][1], bhf[in2 + 1][0], bhf[in2 + 1][1], sKh + off);
            ldsm4(blf[in2][0], blf[in2][1], blf[in2 + 1][0], blf[in2 + 1][1], sKl + off);
        }
        #pragma unroll
        for (int im = 0; im < 4; im++) {
            int arow = wm * 64 + im * 16 + (lane & 15);
            int acb = (ks * 16 + ((lane >> 4) << 3)) * 2;
            uint32_t off = SW128(arow * 128 + acb);
            uint32_t ah[4], al[4];
            ldsm4(ah[0], ah[1], ah[2], ah[3], sQh + off);
            ldsm4(al[0], al[1], al[2], al[3], sQl + off);
            #pragma unroll
            for (int in = 0; in < 4; in++) {
                mmab(acc[im][in], ah, bhf[in]);
                mmab(acc[im][in], al, bhf[in]);
                mmab(acc[im][in], ah, blf[in]);
            }
        }
    }

    int b = bh >> 4;
    int g = lane >> 2, c2 = (lane & 3) * 2;
    #pragma unroll
    for (int im = 0; im < 4; im++)
        #pragma unroll
        for (int hh = 0; hh < 2; hh++) {
            int q = q0 + wm * 64 + im * 16 + g + hh * 8;
            float vals[8];
            #pragma unroll
            for (int in = 0; in < 4; in++) {
                int kc = k0 + wn * 32 + in * 8 + c2;
                unsigned short mk = *(const unsigned short*)&mask[(size_t)b * Sq * Sq + (size_t)q * Sq + kc];
                vals[in * 2]     = (mk & 0xffu) ? -1e9f : acc[im][in][hh * 2] * 0.125f;
                vals[in * 2 + 1] = ((mk >> 8) & 0xffu) ? -1e9f : acc[im][in][hh * 2 + 1] * 0.125f;
            }
            float m = vals[0];
            #pragma unroll
            for (int i = 1; i < 8; i++) m = fmaxf(m, vals[i]);
            m = fmaxf(m, __shfl_xor_sync(0xffffffffu, m, 1));
            m = fmaxf(m, __shfl_xor_sync(0xffffffffu, m, 2));
            float s = 0.0f;
            #pragma unroll
            for (int i = 0; i < 8; i++) s += __expf(vals[i] - m);
            s += __shfl_xor_sync(0xffffffffu, s, 1);
            s += __shfl_xor_sync(0xffffffffu, s, 2);
            if ((lane & 3) == 0)
                g_pstat[((size_t)bh * Sq + q) * 64 + blockIdx.x * 4 + wn] = make_float2(m, s);
        }
}

// ---------------- fold 64 partials per row -> rowmax, rinv ----------------
__global__ void __launch_bounds__(256) reduce_stats() {
    int r = blockIdx.x * 8 + (threadIdx.x >> 5);
    int lane = threadIdx.x & 31;
    float2 a = g_pstat[(size_t)r * 64 + lane];
    float2 b = g_pstat[(size_t)r * 64 + 32 + lane];
    float m = fmaxf(a.x, b.x);
    #pragma unroll
    for (int o = 16; o; o >>= 1) m = fmaxf(m, __shfl_xor_sync(0xffffffffu, m, o));
    float s = a.y * __expf(a.x - m) + b.y * __expf(b.x - m);
    #pragma unroll
    for (int o = 16; o; o >>= 1) s += __shfl_xor_sync(0xffffffffu, s, o);
    if (lane == 0) { g_rowmax[r] = m; g_rinv[r] = 1.0f / s; }
}

// ---------------- pass B: recompute QK^T, write probs, P@V ----------------
// V uses hi plane only (P·bf16(V)); K x4 loads; V x4.trans loads.
// smem: Qh 16K | Ql 16K | 2 stages x {Kh 8K | Kl 8K | Vh 8K} = 80KB
__global__ void __launch_bounds__(256, 2) fused_pv(const unsigned char* __restrict__ mask,
                                                   float* __restrict__ attn) {
    extern __shared__ char smraw[];
    int t = threadIdx.x, lane = t & 31, w = t >> 5;
    int g = lane >> 2, c2 = (lane & 3) * 2;
    int bh = blockIdx.y, q0 = blockIdx.x * 128;
    size_t base = (size_t)bh * Sq * 64;
    uint32_t sBase = smaddr(smraw);
    uint32_t sQh = sBase, sQl = sBase + 16384;

    // Q tile staging (one-time)
    {
        int qr = t >> 1, qc = (t & 1) * 32;
        #pragma unroll
        for (int p = 0; p < 4; p++) {
            size_t qi = base + (size_t)(q0 + qr) * 64 + qc + p * 8;
            uint32_t off = SW128(qr * 128 + (qc + p * 8) * 2);
            *(uint4*)(smraw + off) = *(const uint4*)&g_Qh[qi];
            *(uint4*)(smraw + 16384 + off) = *(const uint4*)&g_Ql[qi];
        }
    }

    // K/V staging: 64 rows x 128B per plane; 4 thr/row, 2 x 16B chunks each
    int kr = t >> 2, kc = (t & 3) * 16;
    uint32_t soff0 = SW128(kr * 128 + kc * 2);
    uint32_t soff1 = SW128(kr * 128 + kc * 2 + 16);
    {
        uint32_t s0 = sBase + 32768;
        size_t gi = base + (size_t)kr * 64 + kc;
        cpasync16(s0 + soff0,         &g_Kh[gi]);     cpasync16(s0 + soff1,         &g_Kh[gi + 8]);
        cpasync16(s0 + 8192 + soff0,  &g_Kl[gi]);     cpasync16(s0 + 8192 + soff1,  &g_Kl[gi + 8]);
        cpasync16(s0 + 16384 + soff0, &g_Vh[gi]);     cpasync16(s0 + 16384 + soff1, &g_Vh[gi + 8]);
        cp_commit();
    }

    int qa = q0 + w * 16 + g, qb = qa + 8;
    float mxa = g_rowmax[bh * Sq + qa], ria = g_rinv[bh * Sq + qa];
    float mxb = g_rowmax[bh * Sq + qb], rib = g_rinv[bh * Sq + qb];
    size_t rowa = (size_t)bh * Sq * Sq + (size_t)qa * Sq;
    size_t rowb = (size_t)bh * Sq * Sq + (size_t)qb * Sq;
    const unsigned char* mrowa = mask + (size_t)(bh >> 4) * Sq * Sq + (size_t)qa * Sq;
    const unsigned char* mrowb = mask + (size_t)(bh >> 4) * Sq * Sq + (size_t)qb * Sq;

    float accc[8][4];
    #pragma unroll
    for (int j = 0; j < 8; j++)
        #pragma unroll
        for (int e = 0; e < 4; e++) accc[j][e] = 0.0f;

    for (int kt = 0; kt < 32; kt++) {
        int buf = kt & 1;
        cp_wait0();
        __syncthreads();
        if (kt < 31) {
            uint32_t sn = sBase + 32768 + (buf ^ 1) * 24576;
            size_t gi = base + (size_t)((kt + 1) * 64 + kr) * 64 + kc;
            cpasync16(sn + soff0,         &g_Kh[gi]);     cpasync16(sn + soff1,         &g_Kh[gi + 8]);
            cpasync16(sn + 8192 + soff0,  &g_Kl[gi]);     cpasync16(sn + 8192 + soff1,  &g_Kl[gi + 8]);
            cpasync16(sn + 16384 + soff0, &g_Vh[gi]);     cpasync16(sn + 16384 + soff1, &g_Vh[gi + 8]);
            cp_commit();
        }
        uint32_t sKh = sBase + 32768 + buf * 24576, sKl = sKh + 8192, sVh = sKh + 16384;

        // ---- S = Q K^T (3-term) ----
        float accs[8][4];
        #pragma unroll
        for (int j = 0; j < 8; j++)
            #pragma unroll
            for (int e = 0; e < 4; e++) accs[j][e] = 0.0f;
        #pragma unroll
        for (int ks = 0; ks < 4; ks++) {
            int arow = w * 16 + (lane & 15);
            int acb = (ks * 16 + ((lane >> 4) << 3)) * 2;
            uint32_t offa = SW128(arow * 128 + acb);
            uint32_t ah[4], al[4];
            ldsm4(ah[0], ah[1], ah[2], ah[3], sQh + offa);
            ldsm4(al[0], al[1], al[2], al[3], sQl + offa);
            #pragma unroll
            for (int in2 = 0; in2 < 8; in2 += 2) {
                int nrow = (in2 + (lane >> 4)) * 8 + (lane & 7);
                int cb = (ks * 16 + (lane & 8)) * 2;
                uint32_t off = SW128(nrow * 128 + cb);
                uint32_t k0r, k1r, k2r, k3r, l0r, l1r, l2r, l3r;
                ldsm4(k0r, k1r, k2r, k3r, sKh + off);
                ldsm4(l0r, l1r, l2r, l3r, sKl + off);
                uint32_t bh0[2] = {k0r, k1r}, bh1[2] = {k2r, k3r};
                uint32_t bl0[2] = {l0r, l1r}, bl1[2] = {l2r, l3r};
                mmab(accs[in2], ah, bh0); mmab(accs[in2], al, bh0); mmab(accs[in2], ah, bl0);
                mmab(accs[in2 + 1], ah, bh1); mmab(accs[in2 + 1], al, bh1); mmab(accs[in2 + 1], ah, bl1);
            }
        }

        // ---- epilogue + PV (2-term: P * bf16(V)) ----
        #pragma unroll
        for (int ks = 0; ks < 4; ks++) {
            uint32_t ahp[4], alp[4];
            #pragma unroll
            for (int half = 0; half < 2; half++) {
                int in = 2 * ks + half;
                int kcol = kt * 64 + in * 8 + c2;
                unsigned short mka = *(const unsigned short*)&mrowa[kcol];
                unsigned short mkb = *(const unsigned short*)&mrowb[kcol];
                float fa0 = (mka & 0xffu) ? -1e9f : accs[in][0] * 0.125f;
                float fa1 = ((mka >> 8) & 0xffu) ? -1e9f : accs[in][1] * 0.125f;
                float fb0 = (mkb & 0xffu) ? -1e9f : accs[in][2] * 0.125f;
                float fb1 = ((mkb >> 8) & 0xffu) ? -1e9f : accs[in][3] * 0.125f;
                float pa0 = __expf(fa0 - mxa) * ria;
                float pa1 = __expf(fa1 - mxa) * ria;
                float pb0 = __expf(fb0 - mxb) * rib;
                float pb1 = __expf(fb1 - mxb) * rib;
                *(float2*)&attn[rowa + kcol] = make_float2(pa0, pa1);
                *(float2*)&attn[rowb + kcol] = make_float2(pb0, pb1);
                pk2bf(pa0, pa1, ahp[half * 2], alp[half * 2]);
                pk2bf(pb0, pb1, ahp[half * 2 + 1], alp[half * 2 + 1]);
            }
            #pragma unroll
            for (int jn2 = 0; jn2 < 8; jn2 += 2) {
                int krow = ks * 16 + (lane & 15);
                int col = (jn2 + (lane >> 4)) * 16;
                uint32_t off = SW128(krow * 128 + col);
                uint32_t v0, v1, v2, v3;
                ldsm4t(v0, v1, v2, v3, sVh + off);
                uint32_t bv0[2] = {v0, v1}, bv1[2] = {v2, v3};
                mmab(accc[jn2], ahp, bv0); mmab(accc[jn2], alp, bv0);
                mmab(accc[jn2 + 1], ahp, bv1); mmab(accc[jn2 + 1], alp, bv1);
            }
        }
    }

    int b = bh >> 4, h = bh & 15;
    #pragma unroll
    for (int jn = 0; jn < 8; jn++)
        #pragma unroll
        for (int hh = 0; hh < 2; hh++) {
            int q = q0 + w * 16 + g + hh * 8;
            int n = jn * 8 + c2;
            float2 v = make_float2(accc[jn][hh * 2], accc[jn][hh * 2 + 1]);
            *(float2*)&g_ctx[(size_t)(b * Sq + q) * 1024 + h * 64 + n] = v;
        }
}

// ---------------- residual + LayerNorm ----------------
__global__ void __launch_bounds__(256) ln_kernel(const float* __restrict__ inQ,
                                                 const float* __restrict__ gamma,
                                                 const float* __restrict__ beta,
                                                 float* __restrict__ out) {
    int m = blockIdx.x, t = threadIdx.x;
    size_t base = (size_t)m * 1024;
    float x[4];
    float s = 0.0f;
    #pragma unroll
    for (int i = 0; i < 4; i++) {
        int c = i * 256 + t;
        x[i] = g_proj[base + c] + inQ[base + c];
        s += x[i];
    }
    s = block_sum(s);
    float mu = s * (1.0f / 1024.0f);
    float s2 = 0.0f;
    #pragma unroll
    for (int i = 0; i < 4; i++) { float d = x[i] - mu; s2 += d * d; }
    s2 = block_sum(s2);
    float rstd = rsqrtf(s2 * (1.0f / 1024.0f) + 1e-5f);
    #pragma unroll
    for (int i = 0; i < 4; i++) {
        int c = i * 256 + t;
        out[base + c] = (x[i] - mu) * rstd * gamma[c] + beta[c];
    }
}

// ---------------- launch ----------------
extern "C" void kernel_launch(void* const* d_in, const int* in_sizes, int n_in,
                              void* d_out, int out_size) {
    const float* inQ = (const float*)d_in[0];
    const float* inK = (const float*)d_in[1];
    const float* inV = (const float*)d_in[2];
    const unsigned char* mask = (const unsigned char*)d_in[3];
    const float* wQ = (const float*)d_in[4];
    const float* wK = (const float*)d_in[5];
    const float* wV = (const float*)d_in[6];
    const float* wO = (const float*)d_in[7];
    const float* gamma = (const float*)d_in[8];
    const float* beta = (const float*)d_in[9];
    float* out = (float*)d_out;
    float* attn = out + (size_t)Bq * Sq * Eq;

    const int GEMM_SMEM = 131072;
    const int SC_SMEM   = 65536;
    const int FP_SMEM   = 81920;   // Q 32KB + 2 x 24KB KV stages
    cudaFuncSetAttribute(gemm8192, cudaFuncAttributeMaxDynamicSharedMemorySize, GEMM_SMEM);
    cudaFuncSetAttribute(scores_stats, cudaFuncAttributeMaxDynamicSharedMemorySize, SC_SMEM);
    cudaFuncSetAttribute(fused_pv, cudaFuncAttributeMaxDynamicSharedMemorySize, FP_SMEM);

    gemm8192<<<dim3(8, 64, 3), 256, GEMM_SMEM>>>(inQ, inK, inV, wQ, wK, wV, 0);
    scores_stats<<<dim3(16, 16, 64), 256, SC_SMEM>>>(mask);
    reduce_stats<<<Bq * Hq * Sq / 8, 256>>>();
    fused_pv<<<dim3(16, 64), 256, FP_SMEM>>>(mask, attn);
    gemm8192<<<dim3(8, 64, 1), 256, GEMM_SMEM>>>(nullptr, nullptr, nullptr, wO, nullptr, nullptr, 3);
    ln_kernel<<<Bq * Sq, 256>>>(inQ, gamma, beta, out);
}